// round 15
// baseline (speedup 1.0000x reference)
#include <cuda_runtime.h>
#include <cuda_fp16.h>
#include <math.h>
#include <stdint.h>

#define TT  4096   // B*S
#define HH  768
#define SS  512
#define BB  8
#define NHH 12
#define DHH 64
#define II  3072
#define EE  8
#define ENT 8192   // TT * TOPK

// ---------------- scratch (static device allocations; no cudaMalloc) --------
__device__ float g_preln[TT * HH];
__device__ __half g_xlh[TT * HH];           // xl fp16 (FFN A operand)
__device__ __half g_xsh[TT * HH];           // X fp16 (QKV A operand)
__device__ __half g_qh[TT * HH];            // Q fp16, [B*NH][S][DH]
__device__ __half g_kh[TT * HH];            // K fp16
__device__ __half g_vh[TT * HH];            // V fp16
__device__ __half g_ch[TT * HH];            // ctx fp16 [T][H] (proj A)
__device__ __half g_hh[(size_t)ENT * II];   // FFN hidden h = gelu(u)*gate, fp16
__device__ __half g_wqkvh[3 * HH * HH];     // [Wq;Wk;Wv] fp16, each [768 k][768 n]
__device__ __half g_woh[HH * HH];           // Wo fp16 [768 k][768 n]
__device__ __half g_wuh[(size_t)EE * HH * II];  // W_up  fp16 [E][H k][I n]
__device__ __half g_wnh[(size_t)EE * HH * II];  // W_new fp16
__device__ __half g_wdh[(size_t)EE * II * HH];  // W_down fp16 [E][I k][H n]
__device__ int   g_cnt[EE];
__device__ int   g_off[EE];
__device__ int   g_cur[EE];
__device__ int   g_etok[ENT];
__device__ float g_ew[ENT];
__device__ int   g_ti[TT * 2];
__device__ float g_tw[TT * 2];

// ======================= asm helpers (portable sm_80+) =======================
__device__ __forceinline__ uint32_t smem_u32(const void* p) {
    uint32_t a;
    asm("{ .reg .u64 t; cvta.to.shared.u64 t, %1; cvt.u32.u64 %0, t; }" : "=r"(a) : "l"(p));
    return a;
}
__device__ __forceinline__ void ldsm4(uint32_t& r0, uint32_t& r1, uint32_t& r2, uint32_t& r3,
                                      uint32_t addr) {
    asm volatile("ldmatrix.sync.aligned.m8n8.x4.shared.b16 {%0,%1,%2,%3}, [%4];"
                 : "=r"(r0), "=r"(r1), "=r"(r2), "=r"(r3) : "r"(addr));
}
__device__ __forceinline__ void ldsm4t(uint32_t& r0, uint32_t& r1, uint32_t& r2, uint32_t& r3,
                                       uint32_t addr) {
    asm volatile("ldmatrix.sync.aligned.m8n8.x4.trans.shared.b16 {%0,%1,%2,%3}, [%4];"
                 : "=r"(r0), "=r"(r1), "=r"(r2), "=r"(r3) : "r"(addr));
}
__device__ __forceinline__ void mma16816(float* c, const uint32_t* a, const uint32_t* b) {
    asm volatile(
        "mma.sync.aligned.m16n8k16.row.col.f32.f16.f16.f32 "
        "{%0,%1,%2,%3}, {%4,%5,%6,%7}, {%8,%9}, {%0,%1,%2,%3};"
        : "+f"(c[0]), "+f"(c[1]), "+f"(c[2]), "+f"(c[3])
        : "r"(a[0]), "r"(a[1]), "r"(a[2]), "r"(a[3]), "r"(b[0]), "r"(b[1]));
}
__device__ __forceinline__ void cpasync16(uint32_t saddr, const void* gaddr) {
    asm volatile("cp.async.cg.shared.global [%0], [%1], 16;" :: "r"(saddr), "l"(gaddr));
}
#define CP_COMMIT() asm volatile("cp.async.commit_group;" ::: "memory")
#define CP_WAIT1()  asm volatile("cp.async.wait_group 1;" ::: "memory")
#define CP_WAIT0()  asm volatile("cp.async.wait_group 0;" ::: "memory")

// xor-swizzled smem byte offset for a [rows x 64 halves] tile (row = 128B, 8 chunks)
__device__ __forceinline__ uint32_t fswz(int m, int c) {
    return (uint32_t)(m * 128 + ((c ^ (m & 7)) << 4));
}
// xor-swizzled smem byte offset for a [k x 128 halves] B tile (row = 256B, 16 chunks)
__device__ __forceinline__ uint32_t bswz(int k, int c) {
    return (uint32_t)(k * 256 + ((c ^ (k & 7)) << 4));
}
__device__ __forceinline__ uint32_t pack2(float v0, float v1) {
    __half2 h = __halves2half2(__float2half_rn(v0), __float2half_rn(v1));
    return *(uint32_t*)&h;
}

// ============ elementwise fp32 -> fp16 convert (pure streaming) ==============
__global__ void fconv(const float* __restrict__ src, __half* __restrict__ h) {
    size_t i = ((size_t)blockIdx.x * 256 + threadIdx.x) * 4;
    float4 v = *(const float4*)(src + i);
    *(uint32_t*)(h + i)     = pack2(v.x, v.y);
    *(uint32_t*)(h + i + 2) = pack2(v.z, v.w);
}

// ============ unified fp16 3-stage pipelined HMMA GEMM (K-slab 64) ===========
// B operand is [K][N] row-major fp16, loaded via ldsm4t. All 1-term fp16.
// MODE 0: QKV  -> Q/K/V fp16
// MODE 1: PROJ -> g_preln (+bo+X)
// MODE 2: DOWN -> atomicAdd out
template<int MODE>
__global__ void __launch_bounds__(256, 2) hgemm(
    const float* __restrict__ p0, const float* __restrict__ p1,
    const float* __restrict__ p2, float* __restrict__ pout) {

    constexpr int KD = (MODE == 2) ? II : HH;   // A K-dim
    constexpr int NS = KD / 64;
    constexpr uint32_t STG = 32768;             // A 16K + B 16K per stage

    int e = 0, base = 0, end = 0, m0 = 0, n0;
    if (MODE == 2) {
        e = blockIdx.y / 6;
        n0 = (blockIdx.y % 6) * 128;
        base = g_off[e] + blockIdx.x * 128;
        end  = g_off[e] + g_cnt[e];
        if (base >= end) return;
    } else {
        m0 = blockIdx.y * 128;
        n0 = blockIdx.x * 128;
    }

    extern __shared__ char dyn[];
    __shared__ int   s_tok[128];
    __shared__ float s_w[128];

    int tid = threadIdx.x, lane = tid & 31, wid = tid >> 5;
    int wm = wid & 1, wn = wid >> 1;

    if (MODE == 2 && tid < 128) {
        int r = min(base + tid, end - 1);
        s_tok[tid] = g_etok[r];
        s_w[tid]   = g_ew[r];
    }
    __syncthreads();

    const __half *Bh, *Ah;
    int nb;
    if (MODE == 0) {
        int which = n0 / HH;
        Bh = g_wqkvh + (size_t)which * HH * HH;
        Ah = g_xsh;
        nb = n0 - which * HH;
    } else if (MODE == 1) {
        Bh = g_woh; Ah = g_ch; nb = n0;
    } else {
        Bh = g_wdh + (size_t)e * II * HH;
        Ah = g_hh;  nb = n0;
    }

    uint32_t sbase = smem_u32(dyn);

    auto issue = [&](int slab, int st) {
        int k0 = slab * 64;
        uint32_t sb = sbase + st * STG;
#pragma unroll
        for (int i = 0; i < 4; i++) {
            int c = tid + i * 256;
            {   // A tile [128 m][64 k]
                int m = c >> 3, kc = c & 7;
                uint32_t so = sb + fswz(m, kc);
                int koff = k0 + kc * 8;
                size_t aoff;
                if (MODE < 2) aoff = (size_t)(m0 + m) * KD;
                else          aoff = (size_t)min(base + m, end - 1) * KD;
                cpasync16(so, Ah + aoff + koff);
            }
            {   // B tile [64 k][128 n]
                int k = c >> 4, cb = c & 15;
                uint32_t bo = sb + 16384 + bswz(k, cb);
                size_t go = (size_t)(k0 + k) * HH + nb + cb * 8;
                cpasync16(bo, Bh + go);
            }
        }
    };

    int j = lane >> 3, rr = lane & 7;
    int amRow = wm * 64 + (j & 1) * 8 + rr;
    int akSel = j >> 1;
    float C[4][4][4] = {};

    issue(0, 0);
    CP_COMMIT();
    if (NS > 1) { issue(1, 1); CP_COMMIT(); }

    for (int s = 0; s < NS; s++) {
        int st = s % 3;
        if (s + 1 < NS) CP_WAIT1(); else CP_WAIT0();
        __syncthreads();
        if (s + 2 < NS) {
            issue(s + 2, (s + 2) % 3);
            CP_COMMIT();
        }
        uint32_t aH = sbase + st * STG;
        uint32_t bH = aH + 16384;
#pragma unroll
        for (int kk = 0; kk < 4; kk++) {
            uint32_t bh[4][2];
#pragma unroll
            for (int f16 = 0; f16 < 2; f16++) {
                int krow = kk * 16 + (j & 1) * 8 + rr;
                int cc = wn * 4 + f16 * 2 + (j >> 1);
                uint32_t o = bswz(krow, cc);
                ldsm4t(bh[f16 * 2][0], bh[f16 * 2][1], bh[f16 * 2 + 1][0], bh[f16 * 2 + 1][1], bH + o);
            }
#pragma unroll
            for (int fm = 0; fm < 4; fm++) {
                int m = amRow + fm * 16;
                int kg = kk * 2 + akSel;
                uint32_t ah[4];
                ldsm4(ah[0], ah[1], ah[2], ah[3], aH + fswz(m, kg));
#pragma unroll
                for (int fn = 0; fn < 4; fn++)
                    mma16816(C[fm][fn], ah, bh[fn]);
            }
        }
        __syncthreads();
    }

    int g = lane >> 2, tig = lane & 3;

    __half* qkv_out = nullptr;
    const float* mbias = nullptr;
    int hcol0 = 0;
    if (MODE == 0) {
        int which = n0 / HH;
        qkv_out = (which == 0) ? g_qh : (which == 1) ? g_kh : g_vh;
        mbias   = (which == 0) ? p0 : (which == 1) ? p1 : p2;
        hcol0   = n0 - which * HH;
    }

#pragma unroll
    for (int fm = 0; fm < 4; fm++) {
        int rowl0 = wm * 64 + fm * 16 + g;
#pragma unroll
        for (int fn = 0; fn < 4; fn++) {
            int coll = wn * 32 + fn * 8 + tig * 2;
#pragma unroll
            for (int hf = 0; hf < 2; hf++) {
                int ml = rowl0 + hf * 8;
                float c0 = C[fm][fn][hf * 2], c1 = C[fm][fn][hf * 2 + 1];
                if (MODE == 0) {
                    int t = m0 + ml;
                    int hcol = hcol0 + coll;
                    int h = hcol >> 6, d = hcol & 63;
                    int b = t >> 9, sI = t & 511;
                    size_t o = (((size_t)(b * NHH + h)) * SS + sI) * DHH + d;
                    *(uint32_t*)(qkv_out + o) = pack2(c0 + mbias[hcol], c1 + mbias[hcol + 1]);
                } else if (MODE == 1) {
                    size_t t = m0 + ml;
                    int col = n0 + coll;
                    float2 xr = *(const float2*)(p1 + t * HH + col);
                    float2 v = {c0 + p0[col] + xr.x, c1 + p0[col + 1] + xr.y};
                    *(float2*)(g_preln + t * HH + col) = v;
                } else {
                    if (base + ml < end) {
                        int col = n0 + coll;
                        int t = s_tok[ml];
                        float w = s_w[ml];
                        const float* eb = p0 + (size_t)e * HH;
                        atomicAdd(pout + (size_t)t * HH + col,     (c0 + eb[col]) * w);
                        atomicAdd(pout + (size_t)t * HH + col + 1, (c1 + eb[col + 1]) * w);
                    }
                }
            }
        }
    }
}

// ====== fused up+gate 3-stage pipelined HMMA grouped GEMM (K-slab 64) ========
#define UPG_SMEM (3 * 49152)
__global__ void __launch_bounds__(256, 1) ffn_upgate(
    const float* __restrict__ bu_, const float* __restrict__ bn_) {
    int e = blockIdx.y / 24;
    int n0 = (blockIdx.y % 24) * 128;
    int base = g_off[e] + blockIdx.x * 128;
    int end  = g_off[e] + g_cnt[e];
    if (base >= end) return;

    extern __shared__ char dyn[];
    __shared__ int s_tok[128];

    int tid = threadIdx.x, lane = tid & 31, wid = tid >> 5;
    int wm = wid & 1, wn = wid >> 1;

    if (tid < 128) s_tok[tid] = g_etok[min(base + tid, end - 1)];
    __syncthreads();

    const __half* Buh = g_wuh + (size_t)e * HH * II;
    const __half* Bnh = g_wnh + (size_t)e * HH * II;
    uint32_t sbase = smem_u32(dyn);

    auto issue = [&](int slab, int st) {
        int k0 = slab * 64;
        uint32_t sb = sbase + st * 49152;
#pragma unroll
        for (int i = 0; i < 4; i++) {
            int c = tid + i * 256;
            {   // A tile [128 m][64 k]
                int m = c >> 3, kc = c & 7;
                uint32_t so = sb + fswz(m, kc);
                size_t aoff = (size_t)s_tok[m] * HH + k0 + kc * 8;
                cpasync16(so, g_xlh + aoff);
            }
            {   // B tiles [64 k][128 n]
                int k = c >> 4, cb = c & 15;
                uint32_t bo = sb + 16384 + bswz(k, cb);
                size_t go = (size_t)(k0 + k) * II + n0 + cb * 8;
                cpasync16(bo,         Buh + go);
                cpasync16(bo + 16384, Bnh + go);
            }
        }
    };

    int j = lane >> 3, rr = lane & 7;
    int amRow = wm * 64 + (j & 1) * 8 + rr;
    int akSel = j >> 1;
    float Cu[4][4][4] = {}, Cn[4][4][4] = {};

    constexpr int NS = HH / 64;
    issue(0, 0);
    CP_COMMIT();
    issue(1, 1);
    CP_COMMIT();

    for (int s = 0; s < NS; s++) {
        int st = s % 3;
        if (s + 1 < NS) CP_WAIT1(); else CP_WAIT0();
        __syncthreads();
        if (s + 2 < NS) {
            issue(s + 2, (s + 2) % 3);
            CP_COMMIT();
        }
        uint32_t aH = sbase + st * 49152;
        uint32_t uH = aH + 16384, nH = aH + 32768;
#pragma unroll
        for (int kk = 0; kk < 4; kk++) {
            uint32_t buh[4][2], bnh[4][2];
#pragma unroll
            for (int f16 = 0; f16 < 2; f16++) {
                int krow = kk * 16 + (j & 1) * 8 + rr;
                int cc = wn * 4 + f16 * 2 + (j >> 1);
                uint32_t o = bswz(krow, cc);
                ldsm4t(buh[f16 * 2][0], buh[f16 * 2][1], buh[f16 * 2 + 1][0], buh[f16 * 2 + 1][1], uH + o);
                ldsm4t(bnh[f16 * 2][0], bnh[f16 * 2][1], bnh[f16 * 2 + 1][0], bnh[f16 * 2 + 1][1], nH + o);
            }
#pragma unroll
            for (int fm = 0; fm < 4; fm++) {
                int m = amRow + fm * 16;
                int kg = kk * 2 + akSel;
                uint32_t ah[4];
                ldsm4(ah[0], ah[1], ah[2], ah[3], aH + fswz(m, kg));
#pragma unroll
                for (int fn = 0; fn < 4; fn++) {
                    mma16816(Cu[fm][fn], ah, buh[fn]);
                    mma16816(Cn[fm][fn], ah, bnh[fn]);
                }
            }
        }
        __syncthreads();
    }

    int g = lane >> 2, tig = lane & 3;
    const float* bu = bu_ + (size_t)e * II;
    const float* bn = bn_ + (size_t)e * II;
#pragma unroll
    for (int fm = 0; fm < 4; fm++) {
        int rowl0 = wm * 64 + fm * 16 + g;
#pragma unroll
        for (int fn = 0; fn < 4; fn++) {
            int col = n0 + wn * 32 + fn * 8 + tig * 2;
            float bu0 = bu[col], bu1 = bu[col + 1];
            float bn0 = bn[col], bn1 = bn[col + 1];
#pragma unroll
            for (int hf = 0; hf < 2; hf++) {
                int r = base + rowl0 + hf * 8;
                if (r < end) {
                    float u0 = Cu[fm][fn][hf * 2] + bu0, u1 = Cu[fm][fn][hf * 2 + 1] + bu1;
                    float h0 = u0 * normcdff(u0) * (Cn[fm][fn][hf * 2] + bn0);
                    float h1 = u1 * normcdff(u1) * (Cn[fm][fn][hf * 2 + 1] + bn1);
                    *(uint32_t*)(g_hh + (size_t)r * II + col) = pack2(h0, h1);
                }
            }
        }
    }
}

// ================= flash attention (fp16 HMMA, online softmax) ===============
#define FL_SMEM (16384 + 2 * 32768)
__global__ void __launch_bounds__(256, 1) flash_attn() {
    int q0 = blockIdx.x * 128;
    int head = blockIdx.y;
    int b = head / NHH, h_ = head % NHH;

    extern __shared__ char dyn[];
    uint32_t sb = smem_u32(dyn);

    const __half* Qh = g_qh + (size_t)head * SS * DHH;
    const __half* Kh = g_kh + (size_t)head * SS * DHH;
    const __half* Vh = g_vh + (size_t)head * SS * DHH;

    int tid = threadIdx.x, lane = tid & 31, wid = tid >> 5;
    int j = lane >> 3, rr = lane & 7;
    int g = lane >> 2, tig = lane & 3;

    auto load_tile = [&](uint32_t dst, const __half* src, int row0) {
#pragma unroll
        for (int i = 0; i < 4; i++) {
            int idx = tid + i * 256;
            int m = idx >> 3, c = idx & 7;
            cpasync16(sb + dst + fswz(m, c), src + (size_t)(row0 + m) * DHH + c * 8);
        }
    };

    load_tile(0, Qh, q0);
    load_tile(16384,         Kh, 0);
    load_tile(16384 + 16384, Vh, 0);
    CP_COMMIT();

    float O[8][4] = {};
    float rm0 = -1e30f, rm1 = -1e30f, l0 = 0.0f, l1 = 0.0f;

    for (int kt = 0; kt < 4; kt++) {
        int st = kt & 1;
        if (kt + 1 < 4) {
            uint32_t nb = 16384 + (st ^ 1) * 32768;
            load_tile(nb,         Kh, (kt + 1) * 128);
            load_tile(nb + 16384, Vh, (kt + 1) * 128);
            CP_COMMIT();
            CP_WAIT1();
        } else {
            CP_WAIT0();
        }
        __syncthreads();

        uint32_t kH = sb + 16384 + st * 32768;
        uint32_t vH = kH + 16384;
        uint32_t qHb = sb;

        float S[16][4] = {};
#pragma unroll
        for (int ks = 0; ks < 4; ks++) {
            int am = wid * 16 + (j & 1) * 8 + rr;
            int ac = 2 * ks + (j >> 1);
            uint32_t ah[4];
            ldsm4(ah[0], ah[1], ah[2], ah[3], qHb + fswz(am, ac));
#pragma unroll
            for (int fnp = 0; fnp < 8; fnp++) {
                int bn = fnp * 16 + (j >> 1) * 8 + rr;
                int bc = 2 * ks + (j & 1);
                uint32_t bo = fswz(bn, bc);
                uint32_t bh[4];
                ldsm4(bh[0], bh[1], bh[2], bh[3], kH + bo);
                mma16816(S[2 * fnp],     ah, bh);
                mma16816(S[2 * fnp + 1], ah, bh + 2);
            }
        }

        float mx0 = -1e30f, mx1 = -1e30f;
#pragma unroll
        for (int fn = 0; fn < 16; fn++) {
            mx0 = fmaxf(mx0, fmaxf(S[fn][0], S[fn][1]));
            mx1 = fmaxf(mx1, fmaxf(S[fn][2], S[fn][3]));
        }
        mx0 = fmaxf(mx0, __shfl_xor_sync(~0u, mx0, 1));
        mx0 = fmaxf(mx0, __shfl_xor_sync(~0u, mx0, 2));
        mx1 = fmaxf(mx1, __shfl_xor_sync(~0u, mx1, 1));
        mx1 = fmaxf(mx1, __shfl_xor_sync(~0u, mx1, 2));
        float nm0 = fmaxf(rm0, mx0 * 0.125f);
        float nm1 = fmaxf(rm1, mx1 * 0.125f);
        float al0 = __expf(rm0 - nm0);
        float al1 = __expf(rm1 - nm1);
        rm0 = nm0; rm1 = nm1;
        float sum0 = 0.0f, sum1 = 0.0f;
#pragma unroll
        for (int fn = 0; fn < 16; fn++) {
            float p0 = __expf(fmaf(S[fn][0], 0.125f, -nm0));
            float p1 = __expf(fmaf(S[fn][1], 0.125f, -nm0));
            float p2 = __expf(fmaf(S[fn][2], 0.125f, -nm1));
            float p3 = __expf(fmaf(S[fn][3], 0.125f, -nm1));
            S[fn][0] = p0; S[fn][1] = p1; S[fn][2] = p2; S[fn][3] = p3;
            sum0 += p0 + p1; sum1 += p2 + p3;
        }
        sum0 += __shfl_xor_sync(~0u, sum0, 1);
        sum0 += __shfl_xor_sync(~0u, sum0, 2);
        sum1 += __shfl_xor_sync(~0u, sum1, 1);
        sum1 += __shfl_xor_sync(~0u, sum1, 2);
        l0 = l0 * al0 + sum0;
        l1 = l1 * al1 + sum1;
#pragma unroll
        for (int fo = 0; fo < 8; fo++) {
            O[fo][0] *= al0; O[fo][1] *= al0;
            O[fo][2] *= al1; O[fo][3] *= al1;
        }

#pragma unroll
        for (int kp = 0; kp < 8; kp++) {
            uint32_t aph[4];
            aph[0] = pack2(S[2 * kp][0],     S[2 * kp][1]);
            aph[1] = pack2(S[2 * kp][2],     S[2 * kp][3]);
            aph[2] = pack2(S[2 * kp + 1][0], S[2 * kp + 1][1]);
            aph[3] = pack2(S[2 * kp + 1][2], S[2 * kp + 1][3]);
#pragma unroll
            for (int dg = 0; dg < 4; dg++) {
                int vrow = kp * 16 + (j & 1) * 8 + rr;
                int vc = dg * 2 + (j >> 1);
                uint32_t vo = fswz(vrow, vc);
                uint32_t vh[4];
                ldsm4t(vh[0], vh[1], vh[2], vh[3], vH + vo);
#pragma unroll
                for (int hg = 0; hg < 2; hg++) {
                    int fo = dg * 2 + hg;
                    mma16816(O[fo], aph, vh + hg * 2);
                }
            }
        }
        __syncthreads();
    }

    float inv0 = 1.0f / l0, inv1 = 1.0f / l1;
    int qr0 = q0 + wid * 16 + g;
    size_t t0 = (size_t)b * SS + qr0;
    size_t t1 = t0 + 8;
#pragma unroll
    for (int fo = 0; fo < 8; fo++) {
        int d = fo * 8 + tig * 2;
        int col = h_ * 64 + d;
        *(uint32_t*)(g_ch + t0 * HH + col) = pack2(O[fo][0] * inv0, O[fo][1] * inv0);
        *(uint32_t*)(g_ch + t1 * HH + col) = pack2(O[fo][2] * inv1, O[fo][3] * inv1);
    }
}

// ====== fused: LN(attn) -> out ; LN(ffn) -> xlh ; router+top2 (one pass) =====
__global__ void lnrouter_kernel(const float* __restrict__ g1, const float* __restrict__ b1,
                                const float* __restrict__ g2, const float* __restrict__ b2,
                                const float* __restrict__ Wr, const float* __restrict__ br,
                                float* __restrict__ dout, float* __restrict__ logits_out) {
    size_t row = blockIdx.x;
    const float* in = g_preln + row * HH;
    int tid = threadIdx.x, lane = tid & 31, wid = tid >> 5;
    float x0 = in[tid], x1 = in[tid + 256], x2 = in[tid + 512];

    __shared__ float red[256];
    __shared__ float racc[8][EE];

    red[tid] = x0 + x1 + x2;
    __syncthreads();
    for (int s = 128; s > 0; s >>= 1) {
        if (tid < s) red[tid] += red[tid + s];
        __syncthreads();
    }
    float mean = red[0] * (1.0f / HH);
    __syncthreads();
    float c0 = x0 - mean, c1 = x1 - mean, c2 = x2 - mean;
    red[tid] = c0 * c0 + c1 * c1 + c2 * c2;
    __syncthreads();
    for (int s = 128; s > 0; s >>= 1) {
        if (tid < s) red[tid] += red[tid + s];
        __syncthreads();
    }
    float inv = 1.0f / sqrtf(red[0] * (1.0f / HH) + 1e-12f);
    __syncthreads();

    float y0 = c0 * inv * g1[tid]       + b1[tid];
    float y1 = c1 * inv * g1[tid + 256] + b1[tid + 256];
    float y2 = c2 * inv * g1[tid + 512] + b1[tid + 512];
    dout[row * HH + tid]       = y0;
    dout[row * HH + tid + 256] = y1;
    dout[row * HH + tid + 512] = y2;

    red[tid] = y0 + y1 + y2;
    __syncthreads();
    for (int s = 128; s > 0; s >>= 1) {
        if (tid < s) red[tid] += red[tid + s];
        __syncthreads();
    }
    float mean2 = red[0] * (1.0f / HH);
    __syncthreads();
    float d0 = y0 - mean2, d1 = y1 - mean2, d2 = y2 - mean2;
    red[tid] = d0 * d0 + d1 * d1 + d2 * d2;
    __syncthreads();
    for (int s = 128; s > 0; s >>= 1) {
        if (tid < s) red[tid] += red[tid + s];
        __syncthreads();
    }
    float inv2 = 1.0f / sqrtf(red[0] * (1.0f / HH) + 1e-12f);

    float z0 = d0 * inv2 * g2[tid]       + b2[tid];
    float z1 = d1 * inv2 * g2[tid + 256] + b2[tid + 256];
    float z2 = d2 * inv2 * g2[tid + 512] + b2[tid + 512];
    g_xlh[row * HH + tid]       = __float2half_rn(z0);
    g_xlh[row * HH + tid + 256] = __float2half_rn(z1);
    g_xlh[row * HH + tid + 512] = __float2half_rn(z2);

    float acc[EE];
#pragma unroll
    for (int e = 0; e < EE; e++) {
        acc[e] = z0 * Wr[(size_t)tid * EE + e]
               + z1 * Wr[(size_t)(tid + 256) * EE + e]
               + z2 * Wr[(size_t)(tid + 512) * EE + e];
    }
#pragma unroll
    for (int e = 0; e < EE; e++)
        for (int o = 16; o > 0; o >>= 1) acc[e] += __shfl_down_sync(~0u, acc[e], o);
    if (lane == 0)
#pragma unroll
        for (int e = 0; e < EE; e++) racc[wid][e] = acc[e];
    __syncthreads();

    if (tid == 0) {
        float lg[EE], mx = -1e30f;
#pragma unroll
        for (int e = 0; e < EE; e++) {
            float v = br[e];
#pragma unroll
            for (int w = 0; w < 8; w++) v += racc[w][e];
            lg[e] = v;
            logits_out[row * EE + e] = v;
            mx = fmaxf(mx, v);
        }
        float p[EE], s = 0.0f;
#pragma unroll
        for (int e = 0; e < EE; e++) { p[e] = expf(lg[e] - mx); s += p[e]; }
        float invs = 1.0f / s;
#pragma unroll
        for (int e = 0; e < EE; e++) p[e] *= invs;

        int i1 = 0;
#pragma unroll
        for (int e = 1; e < EE; e++) if (p[e] > p[i1]) i1 = e;
        int i2 = (i1 == 0) ? 1 : 0;
#pragma unroll
        for (int e = 0; e < EE; e++) if (e != i1 && p[e] > p[i2]) i2 = e;

        float w1 = p[i1], w2 = p[i2], invw = 1.0f / (w1 + w2);
        g_ti[row * 2]     = i1;  g_tw[row * 2]     = w1 * invw;
        g_ti[row * 2 + 1] = i2;  g_tw[row * 2 + 1] = w2 * invw;
        atomicAdd(&g_cnt[i1], 1);
        atomicAdd(&g_cnt[i2], 1);
    }
}

// ================= counters / offsets / scatter ==============================
__global__ void init_kernel() {
    int i = threadIdx.x;
    if (i < EE) { g_cnt[i] = 0; g_cur[i] = 0; }
}

__global__ void offsets_kernel() {
    if (threadIdx.x == 0) {
        int o = 0;
        for (int e = 0; e < EE; e++) { g_off[e] = o; o += g_cnt[e]; }
    }
}

__global__ void scatter_kernel() {
    int t = blockIdx.x * 256 + threadIdx.x;
    if (t >= TT) return;
#pragma unroll
    for (int s = 0; s < 2; s++) {
        int e = g_ti[t * 2 + s];
        int pos = atomicAdd(&g_cur[e], 1);
        int r = g_off[e] + pos;
        g_etok[r] = t;
        g_ew[r] = g_tw[t * 2 + s];
    }
}

// ================= host launcher =============================================
#define HG_SMEM  (3 * 32768)
#define DWN_SMEM (3 * 32768)

extern "C" void kernel_launch(void* const* d_in, const int* in_sizes, int n_in,
                              void* d_out, int out_size) {
    const float* X        = (const float*)d_in[0];
    const float* Wq       = (const float*)d_in[1];
    const float* bq       = (const float*)d_in[2];
    const float* Wk       = (const float*)d_in[3];
    const float* bk       = (const float*)d_in[4];
    const float* Wv       = (const float*)d_in[5];
    const float* bv       = (const float*)d_in[6];
    const float* Wo       = (const float*)d_in[7];
    const float* bo       = (const float*)d_in[8];
    const float* ln_ag    = (const float*)d_in[9];
    const float* ln_ab    = (const float*)d_in[10];
    const float* ln_fg    = (const float*)d_in[11];
    const float* ln_fb    = (const float*)d_in[12];
    const float* Wr       = (const float*)d_in[13];
    const float* br       = (const float*)d_in[14];
    const float* W_up     = (const float*)d_in[15];
    const float* b_up     = (const float*)d_in[16];
    const float* W_new    = (const float*)d_in[17];
    const float* b_new    = (const float*)d_in[18];
    const float* W_down   = (const float*)d_in[19];
    const float* b_down   = (const float*)d_in[20];

    float* out    = (float*)d_out;                    // layer_output [T, H]
    float* logits = out + (size_t)TT * HH;            // router_logits [T, E]

    static cudaStream_t s1;
    static cudaEvent_t evFork, evQKVW, evFFNW;
    static int once = 0;
    if (!once) {
        cudaFuncSetAttribute(hgemm<0>, cudaFuncAttributeMaxDynamicSharedMemorySize, HG_SMEM);
        cudaFuncSetAttribute(hgemm<1>, cudaFuncAttributeMaxDynamicSharedMemorySize, HG_SMEM);
        cudaFuncSetAttribute(hgemm<2>, cudaFuncAttributeMaxDynamicSharedMemorySize, DWN_SMEM);
        cudaFuncSetAttribute(ffn_upgate, cudaFuncAttributeMaxDynamicSharedMemorySize, UPG_SMEM);
        cudaFuncSetAttribute(flash_attn, cudaFuncAttributeMaxDynamicSharedMemorySize, FL_SMEM);
        cudaStreamCreateWithFlags(&s1, cudaStreamNonBlocking);
        cudaEventCreateWithFlags(&evFork, cudaEventDisableTiming);
        cudaEventCreateWithFlags(&evQKVW, cudaEventDisableTiming);
        cudaEventCreateWithFlags(&evFFNW, cudaEventDisableTiming);
        once = 1;
    }

    __half *wqkvh, *woh, *wuh, *wnh, *wdh, *xsh;
    cudaGetSymbolAddress((void**)&wqkvh, g_wqkvh);
    cudaGetSymbolAddress((void**)&woh, g_woh);
    cudaGetSymbolAddress((void**)&wuh, g_wuh);
    cudaGetSymbolAddress((void**)&wnh, g_wnh);
    cudaGetSymbolAddress((void**)&wdh, g_wdh);
    cudaGetSymbolAddress((void**)&xsh, g_xsh);

    // ---- fork side stream for weight prep ----
    cudaEventRecord(evFork, 0);
    cudaStreamWaitEvent(s1, evFork, 0);

    fconv<<<HH * HH / 1024, 256, 0, s1>>>(Wq, wqkvh);
    fconv<<<HH * HH / 1024, 256, 0, s1>>>(Wk, wqkvh + HH * HH);
    fconv<<<HH * HH / 1024, 256, 0, s1>>>(Wv, wqkvh + 2 * HH * HH);
    fconv<<<HH * HH / 1024, 256, 0, s1>>>(Wo, woh);
    cudaEventRecord(evQKVW, s1);
    fconv<<<EE * HH * II / 1024, 256, 0, s1>>>(W_up,  wuh);
    fconv<<<EE * HH * II / 1024, 256, 0, s1>>>(W_new, wnh);
    fconv<<<EE * II * HH / 1024, 256, 0, s1>>>(W_down, wdh);
    cudaEventRecord(evFFNW, s1);

    // ---- main stream: activation prep + attention chain ----
    init_kernel<<<1, 32>>>();
    fconv<<<TT * HH / 1024, 256>>>(X, xsh);

    cudaStreamWaitEvent(0, evQKVW, 0);
    hgemm<0><<<dim3(3 * HH / 128, TT / 128), 256, HG_SMEM>>>(bq, bk, bv, nullptr);
    flash_attn<<<dim3(SS / 128, BB * NHH), 256, FL_SMEM>>>();
    hgemm<1><<<dim3(HH / 128, TT / 128), 256, HG_SMEM>>>(bo, X, nullptr, nullptr);

    lnrouter_kernel<<<TT, 256>>>(ln_ag, ln_ab, ln_fg, ln_fb, Wr, br, out, logits);
    offsets_kernel<<<1, 32>>>();
    scatter_kernel<<<(TT + 255) / 256, 256>>>();

    // ---- join: FFN weights ready before the MoE GEMMs ----
    cudaStreamWaitEvent(0, evFFNW, 0);
    ffn_upgate<<<dim3(32, EE * 24), 256, UPG_SMEM>>>(b_up, b_new);
    hgemm<2><<<dim3(32, EE * 6), 256, DWN_SMEM>>>(b_down, nullptr, nullptr, out);
}

// round 16
// speedup vs baseline: 1.0044x; 1.0044x over previous
#include <cuda_runtime.h>
#include <cuda_fp16.h>
#include <math.h>
#include <stdint.h>

#define TT  4096   // B*S
#define HH  768
#define SS  512
#define BB  8
#define NHH 12
#define DHH 64
#define II  3072
#define EE  8
#define ENT 8192   // TT * TOPK

// ---------------- scratch (static device allocations; no cudaMalloc) --------
__device__ float g_preln[TT * HH];
__device__ __half g_xlh[TT * HH];           // xl fp16 (FFN A operand)
__device__ __half g_xsh[TT * HH];           // X fp16 (QKV A operand)
__device__ __half g_qh[TT * HH];            // Q fp16, [B*NH][S][DH]
__device__ __half g_kh[TT * HH];            // K fp16
__device__ __half g_vh[TT * HH];            // V fp16
__device__ __half g_ch[TT * HH];            // ctx fp16 [T][H] (proj A)
__device__ __half g_hh[(size_t)ENT * II];   // FFN hidden h = gelu(u)*gate, fp16
__device__ __half g_wqkvh[3 * HH * HH];     // [Wq;Wk;Wv] fp16, each [768 k][768 n]
__device__ __half g_woh[HH * HH];           // Wo fp16 [768 k][768 n]
__device__ __half g_wuh[(size_t)EE * HH * II];  // W_up  fp16 [E][H k][I n]
__device__ __half g_wnh[(size_t)EE * HH * II];  // W_new fp16
__device__ __half g_wdh[(size_t)EE * II * HH];  // W_down fp16 [E][I k][H n]
__device__ int   g_cnt[EE];
__device__ int   g_off[EE];
__device__ int   g_cur[EE];
__device__ int   g_etok[ENT];
__device__ float g_ew[ENT];
__device__ int   g_ti[TT * 2];
__device__ float g_tw[TT * 2];

// ======================= asm helpers (portable sm_80+) =======================
__device__ __forceinline__ uint32_t smem_u32(const void* p) {
    uint32_t a;
    asm("{ .reg .u64 t; cvta.to.shared.u64 t, %1; cvt.u32.u64 %0, t; }" : "=r"(a) : "l"(p));
    return a;
}
__device__ __forceinline__ void ldsm4(uint32_t& r0, uint32_t& r1, uint32_t& r2, uint32_t& r3,
                                      uint32_t addr) {
    asm volatile("ldmatrix.sync.aligned.m8n8.x4.shared.b16 {%0,%1,%2,%3}, [%4];"
                 : "=r"(r0), "=r"(r1), "=r"(r2), "=r"(r3) : "r"(addr));
}
__device__ __forceinline__ void ldsm4t(uint32_t& r0, uint32_t& r1, uint32_t& r2, uint32_t& r3,
                                       uint32_t addr) {
    asm volatile("ldmatrix.sync.aligned.m8n8.x4.trans.shared.b16 {%0,%1,%2,%3}, [%4];"
                 : "=r"(r0), "=r"(r1), "=r"(r2), "=r"(r3) : "r"(addr));
}
__device__ __forceinline__ void mma16816(float* c, const uint32_t* a, const uint32_t* b) {
    asm volatile(
        "mma.sync.aligned.m16n8k16.row.col.f32.f16.f16.f32 "
        "{%0,%1,%2,%3}, {%4,%5,%6,%7}, {%8,%9}, {%0,%1,%2,%3};"
        : "+f"(c[0]), "+f"(c[1]), "+f"(c[2]), "+f"(c[3])
        : "r"(a[0]), "r"(a[1]), "r"(a[2]), "r"(a[3]), "r"(b[0]), "r"(b[1]));
}
__device__ __forceinline__ void cpasync16(uint32_t saddr, const void* gaddr) {
    asm volatile("cp.async.cg.shared.global [%0], [%1], 16;" :: "r"(saddr), "l"(gaddr));
}
#define CP_COMMIT() asm volatile("cp.async.commit_group;" ::: "memory")
#define CP_WAIT2()  asm volatile("cp.async.wait_group 2;" ::: "memory")
#define CP_WAIT1()  asm volatile("cp.async.wait_group 1;" ::: "memory")
#define CP_WAIT0()  asm volatile("cp.async.wait_group 0;" ::: "memory")

// xor-swizzled smem byte offset for a [rows x 64 halves] tile (row = 128B, 8 chunks)
__device__ __forceinline__ uint32_t fswz(int m, int c) {
    return (uint32_t)(m * 128 + ((c ^ (m & 7)) << 4));
}
// xor-swizzled smem byte offset for a [k x 128 halves] B tile (row = 256B, 16 chunks)
__device__ __forceinline__ uint32_t bswz(int k, int c) {
    return (uint32_t)(k * 256 + ((c ^ (k & 7)) << 4));
}
__device__ __forceinline__ uint32_t pack2(float v0, float v1) {
    __half2 h = __halves2half2(__float2half_rn(v0), __float2half_rn(v1));
    return *(uint32_t*)&h;
}

// ============ elementwise fp32 -> fp16 convert (pure streaming) ==============
__global__ void fconv(const float* __restrict__ src, __half* __restrict__ h) {
    size_t i = ((size_t)blockIdx.x * 256 + threadIdx.x) * 4;
    float4 v = *(const float4*)(src + i);
    *(uint32_t*)(h + i)     = pack2(v.x, v.y);
    *(uint32_t*)(h + i + 2) = pack2(v.z, v.w);
}

// ============ unified fp16 3-stage pipelined HMMA GEMM (K-slab 64) ===========
// Issue-before-wait: 2 cp.async groups in flight during every compute phase.
// MODE 0: QKV  -> Q/K/V fp16
// MODE 1: PROJ -> g_preln (+bo+X)
// MODE 2: DOWN -> atomicAdd out
template<int MODE>
__global__ void __launch_bounds__(256, 2) hgemm(
    const float* __restrict__ p0, const float* __restrict__ p1,
    const float* __restrict__ p2, float* __restrict__ pout) {

    constexpr int KD = (MODE == 2) ? II : HH;   // A K-dim
    constexpr int NS = KD / 64;
    constexpr uint32_t STG = 32768;             // A 16K + B 16K per stage

    int e = 0, base = 0, end = 0, m0 = 0, n0;
    if (MODE == 2) {
        e = blockIdx.y / 6;
        n0 = (blockIdx.y % 6) * 128;
        base = g_off[e] + blockIdx.x * 128;
        end  = g_off[e] + g_cnt[e];
        if (base >= end) return;
    } else {
        m0 = blockIdx.y * 128;
        n0 = blockIdx.x * 128;
    }

    extern __shared__ char dyn[];
    __shared__ int   s_tok[128];
    __shared__ float s_w[128];

    int tid = threadIdx.x, lane = tid & 31, wid = tid >> 5;
    int wm = wid & 1, wn = wid >> 1;

    if (MODE == 2 && tid < 128) {
        int r = min(base + tid, end - 1);
        s_tok[tid] = g_etok[r];
        s_w[tid]   = g_ew[r];
    }
    __syncthreads();

    const __half *Bh, *Ah;
    int nb;
    if (MODE == 0) {
        int which = n0 / HH;
        Bh = g_wqkvh + (size_t)which * HH * HH;
        Ah = g_xsh;
        nb = n0 - which * HH;
    } else if (MODE == 1) {
        Bh = g_woh; Ah = g_ch; nb = n0;
    } else {
        Bh = g_wdh + (size_t)e * II * HH;
        Ah = g_hh;  nb = n0;
    }

    uint32_t sbase = smem_u32(dyn);

    auto issue = [&](int slab, int st) {
        int k0 = slab * 64;
        uint32_t sb = sbase + st * STG;
#pragma unroll
        for (int i = 0; i < 4; i++) {
            int c = tid + i * 256;
            {   // A tile [128 m][64 k]
                int m = c >> 3, kc = c & 7;
                uint32_t so = sb + fswz(m, kc);
                int koff = k0 + kc * 8;
                size_t aoff;
                if (MODE < 2) aoff = (size_t)(m0 + m) * KD;
                else          aoff = (size_t)min(base + m, end - 1) * KD;
                cpasync16(so, Ah + aoff + koff);
            }
            {   // B tile [64 k][128 n]
                int k = c >> 4, cb = c & 15;
                uint32_t bo = sb + 16384 + bswz(k, cb);
                size_t go = (size_t)(k0 + k) * HH + nb + cb * 8;
                cpasync16(bo, Bh + go);
            }
        }
    };

    int j = lane >> 3, rr = lane & 7;
    int amRow = wm * 64 + (j & 1) * 8 + rr;
    int akSel = j >> 1;
    float C[4][4][4] = {};

    issue(0, 0);
    CP_COMMIT();
    if (NS > 1) { issue(1, 1); CP_COMMIT(); }

    for (int s = 0; s < NS; s++) {
        int st = s % 3;
        if (s + 2 < NS) {
            issue(s + 2, (s + 2) % 3);   // buffer (s-1)%3: consumed before prev barrier
            CP_COMMIT();
            CP_WAIT2();                  // slab s done; s+1, s+2 still in flight
        } else if (s + 1 < NS) {
            CP_WAIT1();
        } else {
            CP_WAIT0();
        }
        __syncthreads();
        uint32_t aH = sbase + st * STG;
        uint32_t bH = aH + 16384;
#pragma unroll
        for (int kk = 0; kk < 4; kk++) {
            uint32_t bh[4][2];
#pragma unroll
            for (int f16 = 0; f16 < 2; f16++) {
                int krow = kk * 16 + (j & 1) * 8 + rr;
                int cc = wn * 4 + f16 * 2 + (j >> 1);
                uint32_t o = bswz(krow, cc);
                ldsm4t(bh[f16 * 2][0], bh[f16 * 2][1], bh[f16 * 2 + 1][0], bh[f16 * 2 + 1][1], bH + o);
            }
#pragma unroll
            for (int fm = 0; fm < 4; fm++) {
                int m = amRow + fm * 16;
                int kg = kk * 2 + akSel;
                uint32_t ah[4];
                ldsm4(ah[0], ah[1], ah[2], ah[3], aH + fswz(m, kg));
#pragma unroll
                for (int fn = 0; fn < 4; fn++)
                    mma16816(C[fm][fn], ah, bh[fn]);
            }
        }
        __syncthreads();
    }

    int g = lane >> 2, tig = lane & 3;

    __half* qkv_out = nullptr;
    const float* mbias = nullptr;
    int hcol0 = 0;
    if (MODE == 0) {
        int which = n0 / HH;
        qkv_out = (which == 0) ? g_qh : (which == 1) ? g_kh : g_vh;
        mbias   = (which == 0) ? p0 : (which == 1) ? p1 : p2;
        hcol0   = n0 - which * HH;
    }

#pragma unroll
    for (int fm = 0; fm < 4; fm++) {
        int rowl0 = wm * 64 + fm * 16 + g;
#pragma unroll
        for (int fn = 0; fn < 4; fn++) {
            int coll = wn * 32 + fn * 8 + tig * 2;
#pragma unroll
            for (int hf = 0; hf < 2; hf++) {
                int ml = rowl0 + hf * 8;
                float c0 = C[fm][fn][hf * 2], c1 = C[fm][fn][hf * 2 + 1];
                if (MODE == 0) {
                    int t = m0 + ml;
                    int hcol = hcol0 + coll;
                    int h = hcol >> 6, d = hcol & 63;
                    int b = t >> 9, sI = t & 511;
                    size_t o = (((size_t)(b * NHH + h)) * SS + sI) * DHH + d;
                    *(uint32_t*)(qkv_out + o) = pack2(c0 + mbias[hcol], c1 + mbias[hcol + 1]);
                } else if (MODE == 1) {
                    size_t t = m0 + ml;
                    int col = n0 + coll;
                    float2 xr = *(const float2*)(p1 + t * HH + col);
                    float2 v = {c0 + p0[col] + xr.x, c1 + p0[col + 1] + xr.y};
                    *(float2*)(g_preln + t * HH + col) = v;
                } else {
                    if (base + ml < end) {
                        int col = n0 + coll;
                        int t = s_tok[ml];
                        float w = s_w[ml];
                        const float* eb = p0 + (size_t)e * HH;
                        atomicAdd(pout + (size_t)t * HH + col,     (c0 + eb[col]) * w);
                        atomicAdd(pout + (size_t)t * HH + col + 1, (c1 + eb[col + 1]) * w);
                    }
                }
            }
        }
    }
}

// ====== fused up+gate 3-stage pipelined HMMA grouped GEMM (K-slab 64) ========
#define UPG_SMEM (3 * 49152)
__global__ void __launch_bounds__(256, 1) ffn_upgate(
    const float* __restrict__ bu_, const float* __restrict__ bn_) {
    int e = blockIdx.y / 24;
    int n0 = (blockIdx.y % 24) * 128;
    int base = g_off[e] + blockIdx.x * 128;
    int end  = g_off[e] + g_cnt[e];
    if (base >= end) return;

    extern __shared__ char dyn[];
    __shared__ int s_tok[128];

    int tid = threadIdx.x, lane = tid & 31, wid = tid >> 5;
    int wm = wid & 1, wn = wid >> 1;

    if (tid < 128) s_tok[tid] = g_etok[min(base + tid, end - 1)];
    __syncthreads();

    const __half* Buh = g_wuh + (size_t)e * HH * II;
    const __half* Bnh = g_wnh + (size_t)e * HH * II;
    uint32_t sbase = smem_u32(dyn);

    auto issue = [&](int slab, int st) {
        int k0 = slab * 64;
        uint32_t sb = sbase + st * 49152;
#pragma unroll
        for (int i = 0; i < 4; i++) {
            int c = tid + i * 256;
            {   // A tile [128 m][64 k]
                int m = c >> 3, kc = c & 7;
                uint32_t so = sb + fswz(m, kc);
                size_t aoff = (size_t)s_tok[m] * HH + k0 + kc * 8;
                cpasync16(so, g_xlh + aoff);
            }
            {   // B tiles [64 k][128 n]
                int k = c >> 4, cb = c & 15;
                uint32_t bo = sb + 16384 + bswz(k, cb);
                size_t go = (size_t)(k0 + k) * II + n0 + cb * 8;
                cpasync16(bo,         Buh + go);
                cpasync16(bo + 16384, Bnh + go);
            }
        }
    };

    int j = lane >> 3, rr = lane & 7;
    int amRow = wm * 64 + (j & 1) * 8 + rr;
    int akSel = j >> 1;
    float Cu[4][4][4] = {}, Cn[4][4][4] = {};

    constexpr int NS = HH / 64;
    issue(0, 0);
    CP_COMMIT();
    issue(1, 1);
    CP_COMMIT();

    for (int s = 0; s < NS; s++) {
        int st = s % 3;
        if (s + 2 < NS) {
            issue(s + 2, (s + 2) % 3);
            CP_COMMIT();
            CP_WAIT2();
        } else if (s + 1 < NS) {
            CP_WAIT1();
        } else {
            CP_WAIT0();
        }
        __syncthreads();
        uint32_t aH = sbase + st * 49152;
        uint32_t uH = aH + 16384, nH = aH + 32768;
#pragma unroll
        for (int kk = 0; kk < 4; kk++) {
            uint32_t buh[4][2], bnh[4][2];
#pragma unroll
            for (int f16 = 0; f16 < 2; f16++) {
                int krow = kk * 16 + (j & 1) * 8 + rr;
                int cc = wn * 4 + f16 * 2 + (j >> 1);
                uint32_t o = bswz(krow, cc);
                ldsm4t(buh[f16 * 2][0], buh[f16 * 2][1], buh[f16 * 2 + 1][0], buh[f16 * 2 + 1][1], uH + o);
                ldsm4t(bnh[f16 * 2][0], bnh[f16 * 2][1], bnh[f16 * 2 + 1][0], bnh[f16 * 2 + 1][1], nH + o);
            }
#pragma unroll
            for (int fm = 0; fm < 4; fm++) {
                int m = amRow + fm * 16;
                int kg = kk * 2 + akSel;
                uint32_t ah[4];
                ldsm4(ah[0], ah[1], ah[2], ah[3], aH + fswz(m, kg));
#pragma unroll
                for (int fn = 0; fn < 4; fn++) {
                    mma16816(Cu[fm][fn], ah, buh[fn]);
                    mma16816(Cn[fm][fn], ah, bnh[fn]);
                }
            }
        }
        __syncthreads();
    }

    int g = lane >> 2, tig = lane & 3;
    const float* bu = bu_ + (size_t)e * II;
    const float* bn = bn_ + (size_t)e * II;
#pragma unroll
    for (int fm = 0; fm < 4; fm++) {
        int rowl0 = wm * 64 + fm * 16 + g;
#pragma unroll
        for (int fn = 0; fn < 4; fn++) {
            int col = n0 + wn * 32 + fn * 8 + tig * 2;
            float bu0 = bu[col], bu1 = bu[col + 1];
            float bn0 = bn[col], bn1 = bn[col + 1];
#pragma unroll
            for (int hf = 0; hf < 2; hf++) {
                int r = base + rowl0 + hf * 8;
                if (r < end) {
                    float u0 = Cu[fm][fn][hf * 2] + bu0, u1 = Cu[fm][fn][hf * 2 + 1] + bu1;
                    float h0 = u0 * normcdff(u0) * (Cn[fm][fn][hf * 2] + bn0);
                    float h1 = u1 * normcdff(u1) * (Cn[fm][fn][hf * 2 + 1] + bn1);
                    *(uint32_t*)(g_hh + (size_t)r * II + col) = pack2(h0, h1);
                }
            }
        }
    }
}

// ================= flash attention (fp16 HMMA, online softmax) ===============
#define FL_SMEM (16384 + 2 * 32768)
__global__ void __launch_bounds__(256, 1) flash_attn() {
    int q0 = blockIdx.x * 128;
    int head = blockIdx.y;
    int b = head / NHH, h_ = head % NHH;

    extern __shared__ char dyn[];
    uint32_t sb = smem_u32(dyn);

    const __half* Qh = g_qh + (size_t)head * SS * DHH;
    const __half* Kh = g_kh + (size_t)head * SS * DHH;
    const __half* Vh = g_vh + (size_t)head * SS * DHH;

    int tid = threadIdx.x, lane = tid & 31, wid = tid >> 5;
    int j = lane >> 3, rr = lane & 7;
    int g = lane >> 2, tig = lane & 3;

    auto load_tile = [&](uint32_t dst, const __half* src, int row0) {
#pragma unroll
        for (int i = 0; i < 4; i++) {
            int idx = tid + i * 256;
            int m = idx >> 3, c = idx & 7;
            cpasync16(sb + dst + fswz(m, c), src + (size_t)(row0 + m) * DHH + c * 8);
        }
    };

    load_tile(0, Qh, q0);
    load_tile(16384,         Kh, 0);
    load_tile(16384 + 16384, Vh, 0);
    CP_COMMIT();

    float O[8][4] = {};
    float rm0 = -1e30f, rm1 = -1e30f, l0 = 0.0f, l1 = 0.0f;

    for (int kt = 0; kt < 4; kt++) {
        int st = kt & 1;
        if (kt + 1 < 4) {
            uint32_t nb = 16384 + (st ^ 1) * 32768;
            load_tile(nb,         Kh, (kt + 1) * 128);
            load_tile(nb + 16384, Vh, (kt + 1) * 128);
            CP_COMMIT();
            CP_WAIT1();
        } else {
            CP_WAIT0();
        }
        __syncthreads();

        uint32_t kH = sb + 16384 + st * 32768;
        uint32_t vH = kH + 16384;
        uint32_t qHb = sb;

        float S[16][4] = {};
#pragma unroll
        for (int ks = 0; ks < 4; ks++) {
            int am = wid * 16 + (j & 1) * 8 + rr;
            int ac = 2 * ks + (j >> 1);
            uint32_t ah[4];
            ldsm4(ah[0], ah[1], ah[2], ah[3], qHb + fswz(am, ac));
#pragma unroll
            for (int fnp = 0; fnp < 8; fnp++) {
                int bn = fnp * 16 + (j >> 1) * 8 + rr;
                int bc = 2 * ks + (j & 1);
                uint32_t bo = fswz(bn, bc);
                uint32_t bh[4];
                ldsm4(bh[0], bh[1], bh[2], bh[3], kH + bo);
                mma16816(S[2 * fnp],     ah, bh);
                mma16816(S[2 * fnp + 1], ah, bh + 2);
            }
        }

        float mx0 = -1e30f, mx1 = -1e30f;
#pragma unroll
        for (int fn = 0; fn < 16; fn++) {
            mx0 = fmaxf(mx0, fmaxf(S[fn][0], S[fn][1]));
            mx1 = fmaxf(mx1, fmaxf(S[fn][2], S[fn][3]));
        }
        mx0 = fmaxf(mx0, __shfl_xor_sync(~0u, mx0, 1));
        mx0 = fmaxf(mx0, __shfl_xor_sync(~0u, mx0, 2));
        mx1 = fmaxf(mx1, __shfl_xor_sync(~0u, mx1, 1));
        mx1 = fmaxf(mx1, __shfl_xor_sync(~0u, mx1, 2));
        float nm0 = fmaxf(rm0, mx0 * 0.125f);
        float nm1 = fmaxf(rm1, mx1 * 0.125f);
        float al0 = __expf(rm0 - nm0);
        float al1 = __expf(rm1 - nm1);
        rm0 = nm0; rm1 = nm1;
        float sum0 = 0.0f, sum1 = 0.0f;
#pragma unroll
        for (int fn = 0; fn < 16; fn++) {
            float p0 = __expf(fmaf(S[fn][0], 0.125f, -nm0));
            float p1 = __expf(fmaf(S[fn][1], 0.125f, -nm0));
            float p2 = __expf(fmaf(S[fn][2], 0.125f, -nm1));
            float p3 = __expf(fmaf(S[fn][3], 0.125f, -nm1));
            S[fn][0] = p0; S[fn][1] = p1; S[fn][2] = p2; S[fn][3] = p3;
            sum0 += p0 + p1; sum1 += p2 + p3;
        }
        sum0 += __shfl_xor_sync(~0u, sum0, 1);
        sum0 += __shfl_xor_sync(~0u, sum0, 2);
        sum1 += __shfl_xor_sync(~0u, sum1, 1);
        sum1 += __shfl_xor_sync(~0u, sum1, 2);
        l0 = l0 * al0 + sum0;
        l1 = l1 * al1 + sum1;
#pragma unroll
        for (int fo = 0; fo < 8; fo++) {
            O[fo][0] *= al0; O[fo][1] *= al0;
            O[fo][2] *= al1; O[fo][3] *= al1;
        }

#pragma unroll
        for (int kp = 0; kp < 8; kp++) {
            uint32_t aph[4];
            aph[0] = pack2(S[2 * kp][0],     S[2 * kp][1]);
            aph[1] = pack2(S[2 * kp][2],     S[2 * kp][3]);
            aph[2] = pack2(S[2 * kp + 1][0], S[2 * kp + 1][1]);
            aph[3] = pack2(S[2 * kp + 1][2], S[2 * kp + 1][3]);
#pragma unroll
            for (int dg = 0; dg < 4; dg++) {
                int vrow = kp * 16 + (j & 1) * 8 + rr;
                int vc = dg * 2 + (j >> 1);
                uint32_t vo = fswz(vrow, vc);
                uint32_t vh[4];
                ldsm4t(vh[0], vh[1], vh[2], vh[3], vH + vo);
#pragma unroll
                for (int hg = 0; hg < 2; hg++) {
                    int fo = dg * 2 + hg;
                    mma16816(O[fo], aph, vh + hg * 2);
                }
            }
        }
        __syncthreads();
    }

    float inv0 = 1.0f / l0, inv1 = 1.0f / l1;
    int qr0 = q0 + wid * 16 + g;
    size_t t0 = (size_t)b * SS + qr0;
    size_t t1 = t0 + 8;
#pragma unroll
    for (int fo = 0; fo < 8; fo++) {
        int d = fo * 8 + tig * 2;
        int col = h_ * 64 + d;
        *(uint32_t*)(g_ch + t0 * HH + col) = pack2(O[fo][0] * inv0, O[fo][1] * inv0);
        *(uint32_t*)(g_ch + t1 * HH + col) = pack2(O[fo][2] * inv1, O[fo][3] * inv1);
    }
}

// ====== fused: LN(attn) -> out ; LN(ffn) -> xlh ; router+top2 (one pass) =====
__global__ void lnrouter_kernel(const float* __restrict__ g1, const float* __restrict__ b1,
                                const float* __restrict__ g2, const float* __restrict__ b2,
                                const float* __restrict__ Wr, const float* __restrict__ br,
                                float* __restrict__ dout, float* __restrict__ logits_out) {
    size_t row = blockIdx.x;
    const float* in = g_preln + row * HH;
    int tid = threadIdx.x, lane = tid & 31, wid = tid >> 5;
    float x0 = in[tid], x1 = in[tid + 256], x2 = in[tid + 512];

    __shared__ float red[256];
    __shared__ float racc[8][EE];

    red[tid] = x0 + x1 + x2;
    __syncthreads();
    for (int s = 128; s > 0; s >>= 1) {
        if (tid < s) red[tid] += red[tid + s];
        __syncthreads();
    }
    float mean = red[0] * (1.0f / HH);
    __syncthreads();
    float c0 = x0 - mean, c1 = x1 - mean, c2 = x2 - mean;
    red[tid] = c0 * c0 + c1 * c1 + c2 * c2;
    __syncthreads();
    for (int s = 128; s > 0; s >>= 1) {
        if (tid < s) red[tid] += red[tid + s];
        __syncthreads();
    }
    float inv = 1.0f / sqrtf(red[0] * (1.0f / HH) + 1e-12f);
    __syncthreads();

    float y0 = c0 * inv * g1[tid]       + b1[tid];
    float y1 = c1 * inv * g1[tid + 256] + b1[tid + 256];
    float y2 = c2 * inv * g1[tid + 512] + b1[tid + 512];
    dout[row * HH + tid]       = y0;
    dout[row * HH + tid + 256] = y1;
    dout[row * HH + tid + 512] = y2;

    red[tid] = y0 + y1 + y2;
    __syncthreads();
    for (int s = 128; s > 0; s >>= 1) {
        if (tid < s) red[tid] += red[tid + s];
        __syncthreads();
    }
    float mean2 = red[0] * (1.0f / HH);
    __syncthreads();
    float d0 = y0 - mean2, d1 = y1 - mean2, d2 = y2 - mean2;
    red[tid] = d0 * d0 + d1 * d1 + d2 * d2;
    __syncthreads();
    for (int s = 128; s > 0; s >>= 1) {
        if (tid < s) red[tid] += red[tid + s];
        __syncthreads();
    }
    float inv2 = 1.0f / sqrtf(red[0] * (1.0f / HH) + 1e-12f);

    float z0 = d0 * inv2 * g2[tid]       + b2[tid];
    float z1 = d1 * inv2 * g2[tid + 256] + b2[tid + 256];
    float z2 = d2 * inv2 * g2[tid + 512] + b2[tid + 512];
    g_xlh[row * HH + tid]       = __float2half_rn(z0);
    g_xlh[row * HH + tid + 256] = __float2half_rn(z1);
    g_xlh[row * HH + tid + 512] = __float2half_rn(z2);

    float acc[EE];
#pragma unroll
    for (int e = 0; e < EE; e++) {
        acc[e] = z0 * Wr[(size_t)tid * EE + e]
               + z1 * Wr[(size_t)(tid + 256) * EE + e]
               + z2 * Wr[(size_t)(tid + 512) * EE + e];
    }
#pragma unroll
    for (int e = 0; e < EE; e++)
        for (int o = 16; o > 0; o >>= 1) acc[e] += __shfl_down_sync(~0u, acc[e], o);
    if (lane == 0)
#pragma unroll
        for (int e = 0; e < EE; e++) racc[wid][e] = acc[e];
    __syncthreads();

    if (tid == 0) {
        float lg[EE], mx = -1e30f;
#pragma unroll
        for (int e = 0; e < EE; e++) {
            float v = br[e];
#pragma unroll
            for (int w = 0; w < 8; w++) v += racc[w][e];
            lg[e] = v;
            logits_out[row * EE + e] = v;
            mx = fmaxf(mx, v);
        }
        float p[EE], s = 0.0f;
#pragma unroll
        for (int e = 0; e < EE; e++) { p[e] = expf(lg[e] - mx); s += p[e]; }
        float invs = 1.0f / s;
#pragma unroll
        for (int e = 0; e < EE; e++) p[e] *= invs;

        int i1 = 0;
#pragma unroll
        for (int e = 1; e < EE; e++) if (p[e] > p[i1]) i1 = e;
        int i2 = (i1 == 0) ? 1 : 0;
#pragma unroll
        for (int e = 0; e < EE; e++) if (e != i1 && p[e] > p[i2]) i2 = e;

        float w1 = p[i1], w2 = p[i2], invw = 1.0f / (w1 + w2);
        g_ti[row * 2]     = i1;  g_tw[row * 2]     = w1 * invw;
        g_ti[row * 2 + 1] = i2;  g_tw[row * 2 + 1] = w2 * invw;
        atomicAdd(&g_cnt[i1], 1);
        atomicAdd(&g_cnt[i2], 1);
    }
}

// ================= counters / offsets / scatter ==============================
__global__ void init_kernel() {
    int i = threadIdx.x;
    if (i < EE) { g_cnt[i] = 0; g_cur[i] = 0; }
}

__global__ void offsets_kernel() {
    if (threadIdx.x == 0) {
        int o = 0;
        for (int e = 0; e < EE; e++) { g_off[e] = o; o += g_cnt[e]; }
    }
}

__global__ void scatter_kernel() {
    int t = blockIdx.x * 256 + threadIdx.x;
    if (t >= TT) return;
#pragma unroll
    for (int s = 0; s < 2; s++) {
        int e = g_ti[t * 2 + s];
        int pos = atomicAdd(&g_cur[e], 1);
        int r = g_off[e] + pos;
        g_etok[r] = t;
        g_ew[r] = g_tw[t * 2 + s];
    }
}

// ================= host launcher =============================================
#define HG_SMEM  (3 * 32768)
#define DWN_SMEM (3 * 32768)

extern "C" void kernel_launch(void* const* d_in, const int* in_sizes, int n_in,
                              void* d_out, int out_size) {
    const float* X        = (const float*)d_in[0];
    const float* Wq       = (const float*)d_in[1];
    const float* bq       = (const float*)d_in[2];
    const float* Wk       = (const float*)d_in[3];
    const float* bk       = (const float*)d_in[4];
    const float* Wv       = (const float*)d_in[5];
    const float* bv       = (const float*)d_in[6];
    const float* Wo       = (const float*)d_in[7];
    const float* bo       = (const float*)d_in[8];
    const float* ln_ag    = (const float*)d_in[9];
    const float* ln_ab    = (const float*)d_in[10];
    const float* ln_fg    = (const float*)d_in[11];
    const float* ln_fb    = (const float*)d_in[12];
    const float* Wr       = (const float*)d_in[13];
    const float* br       = (const float*)d_in[14];
    const float* W_up     = (const float*)d_in[15];
    const float* b_up     = (const float*)d_in[16];
    const float* W_new    = (const float*)d_in[17];
    const float* b_new    = (const float*)d_in[18];
    const float* W_down   = (const float*)d_in[19];
    const float* b_down   = (const float*)d_in[20];

    float* out    = (float*)d_out;                    // layer_output [T, H]
    float* logits = out + (size_t)TT * HH;            // router_logits [T, E]

    static cudaStream_t s1;
    static cudaEvent_t evFork, evQKVW, evFFNW;
    static int once = 0;
    if (!once) {
        cudaFuncSetAttribute(hgemm<0>, cudaFuncAttributeMaxDynamicSharedMemorySize, HG_SMEM);
        cudaFuncSetAttribute(hgemm<1>, cudaFuncAttributeMaxDynamicSharedMemorySize, HG_SMEM);
        cudaFuncSetAttribute(hgemm<2>, cudaFuncAttributeMaxDynamicSharedMemorySize, DWN_SMEM);
        cudaFuncSetAttribute(ffn_upgate, cudaFuncAttributeMaxDynamicSharedMemorySize, UPG_SMEM);
        cudaFuncSetAttribute(flash_attn, cudaFuncAttributeMaxDynamicSharedMemorySize, FL_SMEM);
        cudaStreamCreateWithFlags(&s1, cudaStreamNonBlocking);
        cudaEventCreateWithFlags(&evFork, cudaEventDisableTiming);
        cudaEventCreateWithFlags(&evQKVW, cudaEventDisableTiming);
        cudaEventCreateWithFlags(&evFFNW, cudaEventDisableTiming);
        once = 1;
    }

    __half *wqkvh, *woh, *wuh, *wnh, *wdh, *xsh;
    cudaGetSymbolAddress((void**)&wqkvh, g_wqkvh);
    cudaGetSymbolAddress((void**)&woh, g_woh);
    cudaGetSymbolAddress((void**)&wuh, g_wuh);
    cudaGetSymbolAddress((void**)&wnh, g_wnh);
    cudaGetSymbolAddress((void**)&wdh, g_wdh);
    cudaGetSymbolAddress((void**)&xsh, g_xsh);

    // ---- fork side stream for weight prep ----
    cudaEventRecord(evFork, 0);
    cudaStreamWaitEvent(s1, evFork, 0);

    fconv<<<HH * HH / 1024, 256, 0, s1>>>(Wq, wqkvh);
    fconv<<<HH * HH / 1024, 256, 0, s1>>>(Wk, wqkvh + HH * HH);
    fconv<<<HH * HH / 1024, 256, 0, s1>>>(Wv, wqkvh + 2 * HH * HH);
    fconv<<<HH * HH / 1024, 256, 0, s1>>>(Wo, woh);
    cudaEventRecord(evQKVW, s1);
    fconv<<<EE * HH * II / 1024, 256, 0, s1>>>(W_up,  wuh);
    fconv<<<EE * HH * II / 1024, 256, 0, s1>>>(W_new, wnh);
    fconv<<<EE * II * HH / 1024, 256, 0, s1>>>(W_down, wdh);
    cudaEventRecord(evFFNW, s1);

    // ---- main stream: activation prep + attention chain ----
    init_kernel<<<1, 32>>>();
    fconv<<<TT * HH / 1024, 256>>>(X, xsh);

    cudaStreamWaitEvent(0, evQKVW, 0);
    hgemm<0><<<dim3(3 * HH / 128, TT / 128), 256, HG_SMEM>>>(bq, bk, bv, nullptr);
    flash_attn<<<dim3(SS / 128, BB * NHH), 256, FL_SMEM>>>();
    hgemm<1><<<dim3(HH / 128, TT / 128), 256, HG_SMEM>>>(bo, X, nullptr, nullptr);

    lnrouter_kernel<<<TT, 256>>>(ln_ag, ln_ab, ln_fg, ln_fb, Wr, br, out, logits);
    offsets_kernel<<<1, 32>>>();
    scatter_kernel<<<(TT + 255) / 256, 256>>>();

    // ---- join: FFN weights ready before the MoE GEMMs ----
    cudaStreamWaitEvent(0, evFFNW, 0);
    ffn_upgate<<<dim3(32, EE * 24), 256, UPG_SMEM>>>(b_up, b_new);
    hgemm<2><<<dim3(32, EE * 6), 256, DWN_SMEM>>>(b_down, nullptr, nullptr, out);
}

// round 17
// speedup vs baseline: 1.0912x; 1.0864x over previous
#include <cuda_runtime.h>
#include <cuda_fp16.h>
#include <math.h>
#include <stdint.h>

#define TT  4096   // B*S
#define HH  768
#define SS  512
#define BB  8
#define NHH 12
#define DHH 64
#define II  3072
#define EE  8
#define ENT 8192   // TT * TOPK

// ---------------- scratch (static device allocations; no cudaMalloc) --------
__device__ float g_preln[TT * HH];
__device__ __half g_xlh[TT * HH];           // xl fp16 (FFN A operand)
__device__ __half g_xsh[TT * HH];           // X fp16 (QKV A operand)
__device__ __half g_qh[TT * HH];            // Q fp16, [B*NH][S][DH]
__device__ __half g_kh[TT * HH];            // K fp16
__device__ __half g_vh[TT * HH];            // V fp16
__device__ __half g_ch[TT * HH];            // ctx fp16 [T][H] (proj A)
__device__ __half g_hh[(size_t)ENT * II];   // FFN hidden h = gelu(u)*gate, fp16
__device__ __half g_wqkvh[3 * HH * HH];     // [Wq;Wk;Wv] fp16, each [768 k][768 n]
__device__ __half g_woh[HH * HH];           // Wo fp16 [768 k][768 n]
__device__ __half g_wuh[(size_t)EE * HH * II];  // W_up  fp16 [E][H k][I n]
__device__ __half g_wnh[(size_t)EE * HH * II];  // W_new fp16
__device__ __half g_wdh[(size_t)EE * II * HH];  // W_down fp16 [E][I k][H n]
__device__ int   g_cnt[EE];
__device__ int   g_off[EE];
__device__ int   g_cur[EE];
__device__ int   g_etok[ENT];
__device__ float g_ew[ENT];
__device__ int   g_ti[TT * 2];
__device__ float g_tw[TT * 2];

// ======================= asm helpers (portable sm_80+) =======================
__device__ __forceinline__ uint32_t smem_u32(const void* p) {
    uint32_t a;
    asm("{ .reg .u64 t; cvta.to.shared.u64 t, %1; cvt.u32.u64 %0, t; }" : "=r"(a) : "l"(p));
    return a;
}
__device__ __forceinline__ void ldsm4(uint32_t& r0, uint32_t& r1, uint32_t& r2, uint32_t& r3,
                                      uint32_t addr) {
    asm volatile("ldmatrix.sync.aligned.m8n8.x4.shared.b16 {%0,%1,%2,%3}, [%4];"
                 : "=r"(r0), "=r"(r1), "=r"(r2), "=r"(r3) : "r"(addr));
}
__device__ __forceinline__ void ldsm4t(uint32_t& r0, uint32_t& r1, uint32_t& r2, uint32_t& r3,
                                       uint32_t addr) {
    asm volatile("ldmatrix.sync.aligned.m8n8.x4.trans.shared.b16 {%0,%1,%2,%3}, [%4];"
                 : "=r"(r0), "=r"(r1), "=r"(r2), "=r"(r3) : "r"(addr));
}
__device__ __forceinline__ void mma16816(float* c, const uint32_t* a, const uint32_t* b) {
    asm volatile(
        "mma.sync.aligned.m16n8k16.row.col.f32.f16.f16.f32 "
        "{%0,%1,%2,%3}, {%4,%5,%6,%7}, {%8,%9}, {%0,%1,%2,%3};"
        : "+f"(c[0]), "+f"(c[1]), "+f"(c[2]), "+f"(c[3])
        : "r"(a[0]), "r"(a[1]), "r"(a[2]), "r"(a[3]), "r"(b[0]), "r"(b[1]));
}
__device__ __forceinline__ void cpasync16(uint32_t saddr, const void* gaddr) {
    asm volatile("cp.async.cg.shared.global [%0], [%1], 16;" :: "r"(saddr), "l"(gaddr));
}
#define CP_COMMIT() asm volatile("cp.async.commit_group;" ::: "memory")
#define CP_WAIT1()  asm volatile("cp.async.wait_group 1;" ::: "memory")
#define CP_WAIT0()  asm volatile("cp.async.wait_group 0;" ::: "memory")

// xor-swizzled smem byte offset for a [rows x 64 halves] tile (row = 128B, 8 chunks)
__device__ __forceinline__ uint32_t fswz(int m, int c) {
    return (uint32_t)(m * 128 + ((c ^ (m & 7)) << 4));
}
// xor-swizzled smem byte offset for a [k x 128 halves] B tile (row = 256B, 16 chunks)
__device__ __forceinline__ uint32_t bswz(int k, int c) {
    return (uint32_t)(k * 256 + ((c ^ (k & 7)) << 4));
}
__device__ __forceinline__ uint32_t pack2(float v0, float v1) {
    __half2 h = __halves2half2(__float2half_rn(v0), __float2half_rn(v1));
    return *(uint32_t*)&h;
}

// ============ elementwise fp32 -> fp16 convert (pure streaming) ==============
__global__ void fconv(const float* __restrict__ src, __half* __restrict__ h) {
    size_t i = ((size_t)blockIdx.x * 256 + threadIdx.x) * 4;
    float4 v = *(const float4*)(src + i);
    *(uint32_t*)(h + i)     = pack2(v.x, v.y);
    *(uint32_t*)(h + i + 2) = pack2(v.z, v.w);
}

// ============ unified fp16 2-stage pipelined HMMA GEMM (K-slab 64) ===========
// (R14-proven configuration)
// MODE 0: QKV  -> Q/K/V fp16
// MODE 1: PROJ -> g_preln (+bo+X)
// MODE 2: DOWN -> atomicAdd out
template<int MODE>
__global__ void __launch_bounds__(256, 2) hgemm(
    const float* __restrict__ p0, const float* __restrict__ p1,
    const float* __restrict__ p2, float* __restrict__ pout) {

    constexpr int KD = (MODE == 2) ? II : HH;   // A K-dim
    constexpr int NS = KD / 64;
    constexpr uint32_t STG = 32768;             // A 16K + B 16K per stage

    int e = 0, base = 0, end = 0, m0 = 0, n0;
    if (MODE == 2) {
        e = blockIdx.y / 6;
        n0 = (blockIdx.y % 6) * 128;
        base = g_off[e] + blockIdx.x * 128;
        end  = g_off[e] + g_cnt[e];
        if (base >= end) return;
    } else {
        m0 = blockIdx.y * 128;
        n0 = blockIdx.x * 128;
    }

    extern __shared__ char dyn[];
    __shared__ int   s_tok[128];
    __shared__ float s_w[128];

    int tid = threadIdx.x, lane = tid & 31, wid = tid >> 5;
    int wm = wid & 1, wn = wid >> 1;

    if (MODE == 2 && tid < 128) {
        int r = min(base + tid, end - 1);
        s_tok[tid] = g_etok[r];
        s_w[tid]   = g_ew[r];
    }
    __syncthreads();

    const __half *Bh, *Ah;
    int nb;
    if (MODE == 0) {
        int which = n0 / HH;
        Bh = g_wqkvh + (size_t)which * HH * HH;
        Ah = g_xsh;
        nb = n0 - which * HH;
    } else if (MODE == 1) {
        Bh = g_woh; Ah = g_ch; nb = n0;
    } else {
        Bh = g_wdh + (size_t)e * II * HH;
        Ah = g_hh;  nb = n0;
    }

    uint32_t sbase = smem_u32(dyn);

    auto issue = [&](int slab, int st) {
        int k0 = slab * 64;
        uint32_t sb = sbase + st * STG;
#pragma unroll
        for (int i = 0; i < 4; i++) {
            int c = tid + i * 256;
            {   // A tile [128 m][64 k]
                int m = c >> 3, kc = c & 7;
                uint32_t so = sb + fswz(m, kc);
                int koff = k0 + kc * 8;
                size_t aoff;
                if (MODE < 2) aoff = (size_t)(m0 + m) * KD;
                else          aoff = (size_t)min(base + m, end - 1) * KD;
                cpasync16(so, Ah + aoff + koff);
            }
            {   // B tile [64 k][128 n]
                int k = c >> 4, cb = c & 15;
                uint32_t bo = sb + 16384 + bswz(k, cb);
                size_t go = (size_t)(k0 + k) * HH + nb + cb * 8;
                cpasync16(bo, Bh + go);
            }
        }
    };

    int j = lane >> 3, rr = lane & 7;
    int amRow = wm * 64 + (j & 1) * 8 + rr;
    int akSel = j >> 1;
    float C[4][4][4] = {};

    issue(0, 0);
    CP_COMMIT();
    for (int s = 0; s < NS; s++) {
        int st = s & 1;
        if (s + 1 < NS) {
            issue(s + 1, st ^ 1);
            CP_COMMIT();
            CP_WAIT1();
        } else {
            CP_WAIT0();
        }
        __syncthreads();
        uint32_t aH = sbase + st * STG;
        uint32_t bH = aH + 16384;
#pragma unroll
        for (int kk = 0; kk < 4; kk++) {
            uint32_t bh[4][2];
#pragma unroll
            for (int f16 = 0; f16 < 2; f16++) {
                int krow = kk * 16 + (j & 1) * 8 + rr;
                int cc = wn * 4 + f16 * 2 + (j >> 1);
                uint32_t o = bswz(krow, cc);
                ldsm4t(bh[f16 * 2][0], bh[f16 * 2][1], bh[f16 * 2 + 1][0], bh[f16 * 2 + 1][1], bH + o);
            }
#pragma unroll
            for (int fm = 0; fm < 4; fm++) {
                int m = amRow + fm * 16;
                int kg = kk * 2 + akSel;
                uint32_t ah[4];
                ldsm4(ah[0], ah[1], ah[2], ah[3], aH + fswz(m, kg));
#pragma unroll
                for (int fn = 0; fn < 4; fn++)
                    mma16816(C[fm][fn], ah, bh[fn]);
            }
        }
        __syncthreads();
    }

    int g = lane >> 2, tig = lane & 3;

    __half* qkv_out = nullptr;
    const float* mbias = nullptr;
    int hcol0 = 0;
    if (MODE == 0) {
        int which = n0 / HH;
        qkv_out = (which == 0) ? g_qh : (which == 1) ? g_kh : g_vh;
        mbias   = (which == 0) ? p0 : (which == 1) ? p1 : p2;
        hcol0   = n0 - which * HH;
    }

#pragma unroll
    for (int fm = 0; fm < 4; fm++) {
        int rowl0 = wm * 64 + fm * 16 + g;
#pragma unroll
        for (int fn = 0; fn < 4; fn++) {
            int coll = wn * 32 + fn * 8 + tig * 2;
#pragma unroll
            for (int hf = 0; hf < 2; hf++) {
                int ml = rowl0 + hf * 8;
                float c0 = C[fm][fn][hf * 2], c1 = C[fm][fn][hf * 2 + 1];
                if (MODE == 0) {
                    int t = m0 + ml;
                    int hcol = hcol0 + coll;
                    int h = hcol >> 6, d = hcol & 63;
                    int b = t >> 9, sI = t & 511;
                    size_t o = (((size_t)(b * NHH + h)) * SS + sI) * DHH + d;
                    *(uint32_t*)(qkv_out + o) = pack2(c0 + mbias[hcol], c1 + mbias[hcol + 1]);
                } else if (MODE == 1) {
                    size_t t = m0 + ml;
                    int col = n0 + coll;
                    float2 xr = *(const float2*)(p1 + t * HH + col);
                    float2 v = {c0 + p0[col] + xr.x, c1 + p0[col + 1] + xr.y};
                    *(float2*)(g_preln + t * HH + col) = v;
                } else {
                    if (base + ml < end) {
                        int col = n0 + coll;
                        int t = s_tok[ml];
                        float w = s_w[ml];
                        const float* eb = p0 + (size_t)e * HH;
                        atomicAdd(pout + (size_t)t * HH + col,     (c0 + eb[col]) * w);
                        atomicAdd(pout + (size_t)t * HH + col + 1, (c1 + eb[col + 1]) * w);
                    }
                }
            }
        }
    }
}

// ====== fused up+gate 2-stage HMMA grouped GEMM: N-tile 64, 2 CTAs/SM ========
// Per stage: A [128m][64k] 16KB + Bu [64k][64n] 8KB + Bn 8KB = 32KB.
// Warp tile 32m x 32n; accumulators 64 floats.
#define UPG_SMEM (2 * 32768)
__global__ void __launch_bounds__(256, 2) ffn_upgate(
    const float* __restrict__ bu_, const float* __restrict__ bn_) {
    int e = blockIdx.y / 48;
    int n0 = (blockIdx.y % 48) * 64;
    int base = g_off[e] + blockIdx.x * 128;
    int end  = g_off[e] + g_cnt[e];
    if (base >= end) return;

    extern __shared__ char dyn[];
    __shared__ int s_tok[128];

    int tid = threadIdx.x, lane = tid & 31, wid = tid >> 5;
    int wm = wid >> 1, wn = wid & 1;     // 4 row-groups x 2 col-groups

    if (tid < 128) s_tok[tid] = g_etok[min(base + tid, end - 1)];
    __syncthreads();

    const __half* Buh = g_wuh + (size_t)e * HH * II;
    const __half* Bnh = g_wnh + (size_t)e * HH * II;
    uint32_t sbase = smem_u32(dyn);

    auto issue = [&](int slab, int st) {
        int k0 = slab * 64;
        uint32_t sb = sbase + st * 32768;
        // A tile [128 m][64 k]: 1024 chunks
#pragma unroll
        for (int i = 0; i < 4; i++) {
            int c = tid + i * 256;
            int m = c >> 3, kc = c & 7;
            size_t aoff = (size_t)s_tok[m] * HH + k0 + kc * 8;
            cpasync16(sb + fswz(m, kc), g_xlh + aoff);
        }
        // B tiles [64 k][64 n]: 512 chunks each
#pragma unroll
        for (int i = 0; i < 2; i++) {
            int c = tid + i * 256;
            int k = c >> 3, cb = c & 7;
            uint32_t bo = sb + 16384 + fswz(k, cb);
            size_t go = (size_t)(k0 + k) * II + n0 + cb * 8;
            cpasync16(bo,        Buh + go);
            cpasync16(bo + 8192, Bnh + go);
        }
    };

    int j = lane >> 3, rr = lane & 7;
    int amRow = wm * 32 + (j & 1) * 8 + rr;
    int akSel = j >> 1;
    float Cu[2][4][4] = {}, Cn[2][4][4] = {};

    constexpr int NS = HH / 64;
    issue(0, 0);
    CP_COMMIT();
    for (int s = 0; s < NS; s++) {
        int st = s & 1;
        if (s + 1 < NS) {
            issue(s + 1, st ^ 1);
            CP_COMMIT();
            CP_WAIT1();
        } else {
            CP_WAIT0();
        }
        __syncthreads();
        uint32_t aH = sbase + st * 32768;
        uint32_t uH = aH + 16384, nH = aH + 24576;
#pragma unroll
        for (int kk = 0; kk < 4; kk++) {
            uint32_t buh[4][2], bnh[4][2];
#pragma unroll
            for (int f16 = 0; f16 < 2; f16++) {
                int krow = kk * 16 + (j & 1) * 8 + rr;
                int cc = wn * 4 + f16 * 2 + (j >> 1);
                uint32_t o = fswz(krow, cc);
                ldsm4t(buh[f16 * 2][0], buh[f16 * 2][1], buh[f16 * 2 + 1][0], buh[f16 * 2 + 1][1], uH + o);
                ldsm4t(bnh[f16 * 2][0], bnh[f16 * 2][1], bnh[f16 * 2 + 1][0], bnh[f16 * 2 + 1][1], nH + o);
            }
#pragma unroll
            for (int fm = 0; fm < 2; fm++) {
                int m = amRow + fm * 16;
                int kg = kk * 2 + akSel;
                uint32_t ah[4];
                ldsm4(ah[0], ah[1], ah[2], ah[3], aH + fswz(m, kg));
#pragma unroll
                for (int fn = 0; fn < 4; fn++) {
                    mma16816(Cu[fm][fn], ah, buh[fn]);
                    mma16816(Cn[fm][fn], ah, bnh[fn]);
                }
            }
        }
        __syncthreads();
    }

    int g = lane >> 2, tig = lane & 3;
    const float* bu = bu_ + (size_t)e * II;
    const float* bn = bn_ + (size_t)e * II;
#pragma unroll
    for (int fm = 0; fm < 2; fm++) {
        int rowl0 = wm * 32 + fm * 16 + g;
#pragma unroll
        for (int fn = 0; fn < 4; fn++) {
            int col = n0 + wn * 32 + fn * 8 + tig * 2;
            float bu0 = bu[col], bu1 = bu[col + 1];
            float bn0 = bn[col], bn1 = bn[col + 1];
#pragma unroll
            for (int hf = 0; hf < 2; hf++) {
                int r = base + rowl0 + hf * 8;
                if (r < end) {
                    float u0 = Cu[fm][fn][hf * 2] + bu0, u1 = Cu[fm][fn][hf * 2 + 1] + bu1;
                    float h0 = u0 * normcdff(u0) * (Cn[fm][fn][hf * 2] + bn0);
                    float h1 = u1 * normcdff(u1) * (Cn[fm][fn][hf * 2 + 1] + bn1);
                    *(uint32_t*)(g_hh + (size_t)r * II + col) = pack2(h0, h1);
                }
            }
        }
    }
}

// ================= flash attention (fp16 HMMA, online softmax) ===============
#define FL_SMEM (16384 + 2 * 32768)
__global__ void __launch_bounds__(256, 1) flash_attn() {
    int q0 = blockIdx.x * 128;
    int head = blockIdx.y;
    int b = head / NHH, h_ = head % NHH;

    extern __shared__ char dyn[];
    uint32_t sb = smem_u32(dyn);

    const __half* Qh = g_qh + (size_t)head * SS * DHH;
    const __half* Kh = g_kh + (size_t)head * SS * DHH;
    const __half* Vh = g_vh + (size_t)head * SS * DHH;

    int tid = threadIdx.x, lane = tid & 31, wid = tid >> 5;
    int j = lane >> 3, rr = lane & 7;
    int g = lane >> 2, tig = lane & 3;

    auto load_tile = [&](uint32_t dst, const __half* src, int row0) {
#pragma unroll
        for (int i = 0; i < 4; i++) {
            int idx = tid + i * 256;
            int m = idx >> 3, c = idx & 7;
            cpasync16(sb + dst + fswz(m, c), src + (size_t)(row0 + m) * DHH + c * 8);
        }
    };

    load_tile(0, Qh, q0);
    load_tile(16384,         Kh, 0);
    load_tile(16384 + 16384, Vh, 0);
    CP_COMMIT();

    float O[8][4] = {};
    float rm0 = -1e30f, rm1 = -1e30f, l0 = 0.0f, l1 = 0.0f;

    for (int kt = 0; kt < 4; kt++) {
        int st = kt & 1;
        if (kt + 1 < 4) {
            uint32_t nb = 16384 + (st ^ 1) * 32768;
            load_tile(nb,         Kh, (kt + 1) * 128);
            load_tile(nb + 16384, Vh, (kt + 1) * 128);
            CP_COMMIT();
            CP_WAIT1();
        } else {
            CP_WAIT0();
        }
        __syncthreads();

        uint32_t kH = sb + 16384 + st * 32768;
        uint32_t vH = kH + 16384;
        uint32_t qHb = sb;

        float S[16][4] = {};
#pragma unroll
        for (int ks = 0; ks < 4; ks++) {
            int am = wid * 16 + (j & 1) * 8 + rr;
            int ac = 2 * ks + (j >> 1);
            uint32_t ah[4];
            ldsm4(ah[0], ah[1], ah[2], ah[3], qHb + fswz(am, ac));
#pragma unroll
            for (int fnp = 0; fnp < 8; fnp++) {
                int bn = fnp * 16 + (j >> 1) * 8 + rr;
                int bc = 2 * ks + (j & 1);
                uint32_t bo = fswz(bn, bc);
                uint32_t bh[4];
                ldsm4(bh[0], bh[1], bh[2], bh[3], kH + bo);
                mma16816(S[2 * fnp],     ah, bh);
                mma16816(S[2 * fnp + 1], ah, bh + 2);
            }
        }

        float mx0 = -1e30f, mx1 = -1e30f;
#pragma unroll
        for (int fn = 0; fn < 16; fn++) {
            mx0 = fmaxf(mx0, fmaxf(S[fn][0], S[fn][1]));
            mx1 = fmaxf(mx1, fmaxf(S[fn][2], S[fn][3]));
        }
        mx0 = fmaxf(mx0, __shfl_xor_sync(~0u, mx0, 1));
        mx0 = fmaxf(mx0, __shfl_xor_sync(~0u, mx0, 2));
        mx1 = fmaxf(mx1, __shfl_xor_sync(~0u, mx1, 1));
        mx1 = fmaxf(mx1, __shfl_xor_sync(~0u, mx1, 2));
        float nm0 = fmaxf(rm0, mx0 * 0.125f);
        float nm1 = fmaxf(rm1, mx1 * 0.125f);
        float al0 = __expf(rm0 - nm0);
        float al1 = __expf(rm1 - nm1);
        rm0 = nm0; rm1 = nm1;
        float sum0 = 0.0f, sum1 = 0.0f;
#pragma unroll
        for (int fn = 0; fn < 16; fn++) {
            float p0 = __expf(fmaf(S[fn][0], 0.125f, -nm0));
            float p1 = __expf(fmaf(S[fn][1], 0.125f, -nm0));
            float p2 = __expf(fmaf(S[fn][2], 0.125f, -nm1));
            float p3 = __expf(fmaf(S[fn][3], 0.125f, -nm1));
            S[fn][0] = p0; S[fn][1] = p1; S[fn][2] = p2; S[fn][3] = p3;
            sum0 += p0 + p1; sum1 += p2 + p3;
        }
        sum0 += __shfl_xor_sync(~0u, sum0, 1);
        sum0 += __shfl_xor_sync(~0u, sum0, 2);
        sum1 += __shfl_xor_sync(~0u, sum1, 1);
        sum1 += __shfl_xor_sync(~0u, sum1, 2);
        l0 = l0 * al0 + sum0;
        l1 = l1 * al1 + sum1;
#pragma unroll
        for (int fo = 0; fo < 8; fo++) {
            O[fo][0] *= al0; O[fo][1] *= al0;
            O[fo][2] *= al1; O[fo][3] *= al1;
        }

#pragma unroll
        for (int kp = 0; kp < 8; kp++) {
            uint32_t aph[4];
            aph[0] = pack2(S[2 * kp][0],     S[2 * kp][1]);
            aph[1] = pack2(S[2 * kp][2],     S[2 * kp][3]);
            aph[2] = pack2(S[2 * kp + 1][0], S[2 * kp + 1][1]);
            aph[3] = pack2(S[2 * kp + 1][2], S[2 * kp + 1][3]);
#pragma unroll
            for (int dg = 0; dg < 4; dg++) {
                int vrow = kp * 16 + (j & 1) * 8 + rr;
                int vc = dg * 2 + (j >> 1);
                uint32_t vo = fswz(vrow, vc);
                uint32_t vh[4];
                ldsm4t(vh[0], vh[1], vh[2], vh[3], vH + vo);
#pragma unroll
                for (int hg = 0; hg < 2; hg++) {
                    int fo = dg * 2 + hg;
                    mma16816(O[fo], aph, vh + hg * 2);
                }
            }
        }
        __syncthreads();
    }

    float inv0 = 1.0f / l0, inv1 = 1.0f / l1;
    int qr0 = q0 + wid * 16 + g;
    size_t t0 = (size_t)b * SS + qr0;
    size_t t1 = t0 + 8;
#pragma unroll
    for (int fo = 0; fo < 8; fo++) {
        int d = fo * 8 + tig * 2;
        int col = h_ * 64 + d;
        *(uint32_t*)(g_ch + t0 * HH + col) = pack2(O[fo][0] * inv0, O[fo][1] * inv0);
        *(uint32_t*)(g_ch + t1 * HH + col) = pack2(O[fo][2] * inv1, O[fo][3] * inv1);
    }
}

// ====== fused: LN(attn) -> out ; LN(ffn) -> xlh ; router+top2 (one pass) =====
__global__ void lnrouter_kernel(const float* __restrict__ g1, const float* __restrict__ b1,
                                const float* __restrict__ g2, const float* __restrict__ b2,
                                const float* __restrict__ Wr, const float* __restrict__ br,
                                float* __restrict__ dout, float* __restrict__ logits_out) {
    size_t row = blockIdx.x;
    const float* in = g_preln + row * HH;
    int tid = threadIdx.x, lane = tid & 31, wid = tid >> 5;
    float x0 = in[tid], x1 = in[tid + 256], x2 = in[tid + 512];

    __shared__ float red[256];
    __shared__ float racc[8][EE];

    red[tid] = x0 + x1 + x2;
    __syncthreads();
    for (int s = 128; s > 0; s >>= 1) {
        if (tid < s) red[tid] += red[tid + s];
        __syncthreads();
    }
    float mean = red[0] * (1.0f / HH);
    __syncthreads();
    float c0 = x0 - mean, c1 = x1 - mean, c2 = x2 - mean;
    red[tid] = c0 * c0 + c1 * c1 + c2 * c2;
    __syncthreads();
    for (int s = 128; s > 0; s >>= 1) {
        if (tid < s) red[tid] += red[tid + s];
        __syncthreads();
    }
    float inv = 1.0f / sqrtf(red[0] * (1.0f / HH) + 1e-12f);
    __syncthreads();

    float y0 = c0 * inv * g1[tid]       + b1[tid];
    float y1 = c1 * inv * g1[tid + 256] + b1[tid + 256];
    float y2 = c2 * inv * g1[tid + 512] + b1[tid + 512];
    dout[row * HH + tid]       = y0;
    dout[row * HH + tid + 256] = y1;
    dout[row * HH + tid + 512] = y2;

    red[tid] = y0 + y1 + y2;
    __syncthreads();
    for (int s = 128; s > 0; s >>= 1) {
        if (tid < s) red[tid] += red[tid + s];
        __syncthreads();
    }
    float mean2 = red[0] * (1.0f / HH);
    __syncthreads();
    float d0 = y0 - mean2, d1 = y1 - mean2, d2 = y2 - mean2;
    red[tid] = d0 * d0 + d1 * d1 + d2 * d2;
    __syncthreads();
    for (int s = 128; s > 0; s >>= 1) {
        if (tid < s) red[tid] += red[tid + s];
        __syncthreads();
    }
    float inv2 = 1.0f / sqrtf(red[0] * (1.0f / HH) + 1e-12f);

    float z0 = d0 * inv2 * g2[tid]       + b2[tid];
    float z1 = d1 * inv2 * g2[tid + 256] + b2[tid + 256];
    float z2 = d2 * inv2 * g2[tid + 512] + b2[tid + 512];
    g_xlh[row * HH + tid]       = __float2half_rn(z0);
    g_xlh[row * HH + tid + 256] = __float2half_rn(z1);
    g_xlh[row * HH + tid + 512] = __float2half_rn(z2);

    float acc[EE];
#pragma unroll
    for (int e = 0; e < EE; e++) {
        acc[e] = z0 * Wr[(size_t)tid * EE + e]
               + z1 * Wr[(size_t)(tid + 256) * EE + e]
               + z2 * Wr[(size_t)(tid + 512) * EE + e];
    }
#pragma unroll
    for (int e = 0; e < EE; e++)
        for (int o = 16; o > 0; o >>= 1) acc[e] += __shfl_down_sync(~0u, acc[e], o);
    if (lane == 0)
#pragma unroll
        for (int e = 0; e < EE; e++) racc[wid][e] = acc[e];
    __syncthreads();

    if (tid == 0) {
        float lg[EE], mx = -1e30f;
#pragma unroll
        for (int e = 0; e < EE; e++) {
            float v = br[e];
#pragma unroll
            for (int w = 0; w < 8; w++) v += racc[w][e];
            lg[e] = v;
            logits_out[row * EE + e] = v;
            mx = fmaxf(mx, v);
        }
        float p[EE], s = 0.0f;
#pragma unroll
        for (int e = 0; e < EE; e++) { p[e] = expf(lg[e] - mx); s += p[e]; }
        float invs = 1.0f / s;
#pragma unroll
        for (int e = 0; e < EE; e++) p[e] *= invs;

        int i1 = 0;
#pragma unroll
        for (int e = 1; e < EE; e++) if (p[e] > p[i1]) i1 = e;
        int i2 = (i1 == 0) ? 1 : 0;
#pragma unroll
        for (int e = 0; e < EE; e++) if (e != i1 && p[e] > p[i2]) i2 = e;

        float w1 = p[i1], w2 = p[i2], invw = 1.0f / (w1 + w2);
        g_ti[row * 2]     = i1;  g_tw[row * 2]     = w1 * invw;
        g_ti[row * 2 + 1] = i2;  g_tw[row * 2 + 1] = w2 * invw;
        atomicAdd(&g_cnt[i1], 1);
        atomicAdd(&g_cnt[i2], 1);
    }
}

// ================= counters / offsets / scatter ==============================
__global__ void init_kernel() {
    int i = threadIdx.x;
    if (i < EE) { g_cnt[i] = 0; g_cur[i] = 0; }
}

__global__ void offsets_kernel() {
    if (threadIdx.x == 0) {
        int o = 0;
        for (int e = 0; e < EE; e++) { g_off[e] = o; o += g_cnt[e]; }
    }
}

__global__ void scatter_kernel() {
    int t = blockIdx.x * 256 + threadIdx.x;
    if (t >= TT) return;
#pragma unroll
    for (int s = 0; s < 2; s++) {
        int e = g_ti[t * 2 + s];
        int pos = atomicAdd(&g_cur[e], 1);
        int r = g_off[e] + pos;
        g_etok[r] = t;
        g_ew[r] = g_tw[t * 2 + s];
    }
}

// ================= host launcher =============================================
#define HG_SMEM  (2 * 32768)
#define DWN_SMEM (2 * 32768)

extern "C" void kernel_launch(void* const* d_in, const int* in_sizes, int n_in,
                              void* d_out, int out_size) {
    const float* X        = (const float*)d_in[0];
    const float* Wq       = (const float*)d_in[1];
    const float* bq       = (const float*)d_in[2];
    const float* Wk       = (const float*)d_in[3];
    const float* bk       = (const float*)d_in[4];
    const float* Wv       = (const float*)d_in[5];
    const float* bv       = (const float*)d_in[6];
    const float* Wo       = (const float*)d_in[7];
    const float* bo       = (const float*)d_in[8];
    const float* ln_ag    = (const float*)d_in[9];
    const float* ln_ab    = (const float*)d_in[10];
    const float* ln_fg    = (const float*)d_in[11];
    const float* ln_fb    = (const float*)d_in[12];
    const float* Wr       = (const float*)d_in[13];
    const float* br       = (const float*)d_in[14];
    const float* W_up     = (const float*)d_in[15];
    const float* b_up     = (const float*)d_in[16];
    const float* W_new    = (const float*)d_in[17];
    const float* b_new    = (const float*)d_in[18];
    const float* W_down   = (const float*)d_in[19];
    const float* b_down   = (const float*)d_in[20];

    float* out    = (float*)d_out;                    // layer_output [T, H]
    float* logits = out + (size_t)TT * HH;            // router_logits [T, E]

    static cudaStream_t s1;
    static cudaEvent_t evFork, evQKVW, evFFNW;
    static int once = 0;
    if (!once) {
        cudaFuncSetAttribute(hgemm<0>, cudaFuncAttributeMaxDynamicSharedMemorySize, HG_SMEM);
        cudaFuncSetAttribute(hgemm<1>, cudaFuncAttributeMaxDynamicSharedMemorySize, HG_SMEM);
        cudaFuncSetAttribute(hgemm<2>, cudaFuncAttributeMaxDynamicSharedMemorySize, DWN_SMEM);
        cudaFuncSetAttribute(ffn_upgate, cudaFuncAttributeMaxDynamicSharedMemorySize, UPG_SMEM);
        cudaFuncSetAttribute(flash_attn, cudaFuncAttributeMaxDynamicSharedMemorySize, FL_SMEM);
        cudaStreamCreateWithFlags(&s1, cudaStreamNonBlocking);
        cudaEventCreateWithFlags(&evFork, cudaEventDisableTiming);
        cudaEventCreateWithFlags(&evQKVW, cudaEventDisableTiming);
        cudaEventCreateWithFlags(&evFFNW, cudaEventDisableTiming);
        once = 1;
    }

    __half *wqkvh, *woh, *wuh, *wnh, *wdh, *xsh;
    cudaGetSymbolAddress((void**)&wqkvh, g_wqkvh);
    cudaGetSymbolAddress((void**)&woh, g_woh);
    cudaGetSymbolAddress((void**)&wuh, g_wuh);
    cudaGetSymbolAddress((void**)&wnh, g_wnh);
    cudaGetSymbolAddress((void**)&wdh, g_wdh);
    cudaGetSymbolAddress((void**)&xsh, g_xsh);

    // ---- fork side stream for weight prep ----
    cudaEventRecord(evFork, 0);
    cudaStreamWaitEvent(s1, evFork, 0);

    fconv<<<HH * HH / 1024, 256, 0, s1>>>(Wq, wqkvh);
    fconv<<<HH * HH / 1024, 256, 0, s1>>>(Wk, wqkvh + HH * HH);
    fconv<<<HH * HH / 1024, 256, 0, s1>>>(Wv, wqkvh + 2 * HH * HH);
    fconv<<<HH * HH / 1024, 256, 0, s1>>>(Wo, woh);
    cudaEventRecord(evQKVW, s1);
    fconv<<<EE * HH * II / 1024, 256, 0, s1>>>(W_up,  wuh);
    fconv<<<EE * HH * II / 1024, 256, 0, s1>>>(W_new, wnh);
    fconv<<<EE * II * HH / 1024, 256, 0, s1>>>(W_down, wdh);
    cudaEventRecord(evFFNW, s1);

    // ---- main stream: activation prep + attention chain ----
    init_kernel<<<1, 32>>>();
    fconv<<<TT * HH / 1024, 256>>>(X, xsh);

    cudaStreamWaitEvent(0, evQKVW, 0);
    hgemm<0><<<dim3(3 * HH / 128, TT / 128), 256, HG_SMEM>>>(bq, bk, bv, nullptr);
    flash_attn<<<dim3(SS / 128, BB * NHH), 256, FL_SMEM>>>();
    hgemm<1><<<dim3(HH / 128, TT / 128), 256, HG_SMEM>>>(bo, X, nullptr, nullptr);

    lnrouter_kernel<<<TT, 256>>>(ln_ag, ln_ab, ln_fg, ln_fb, Wr, br, out, logits);
    offsets_kernel<<<1, 32>>>();
    scatter_kernel<<<(TT + 255) / 256, 256>>>();

    // ---- join: FFN weights ready before the MoE GEMMs ----
    cudaStreamWaitEvent(0, evFFNW, 0);
    ffn_upgate<<<dim3(32, EE * 48), 256, UPG_SMEM>>>(b_up, b_new);
    hgemm<2><<<dim3(32, EE * 6), 256, DWN_SMEM>>>(b_down, nullptr, nullptr, out);
}